// round 1
// baseline (speedup 1.0000x reference)
#include <cuda_runtime.h>
#include <math.h>

#define C 1024
#define BATCH 16
#define D 128
#define CB (C*BATCH)
#define NEGV (-1e30f)

// ---------------- scratch (static device memory, no runtime allocation) ----
__device__ float g_h1[BATCH*C*D];      // (b,c,d)  relu(h@W1^T+b1)
__device__ float g_h2[BATCH*C*D];      // (b,c,d)
__device__ float g_P1[BATCH*C*C];      // softmax over axis1 of masked B_t : [b][k][j]
__device__ float g_P2[BATCH*C*C];      // softmax over axis2 of masked B_t : [b][i][k]
__device__ float g_Btt[BATCH*C*C];     // softmax over axis2 of masked B_new
__device__ float g_htmp[CB*D];         // (c,b,d) layout, row r=c*16+b

// ---------------------------------------------------------------- FC kernel
// h1[b,c,e] = relu(h[c,b,:] . W1[e,:] + b1[e]) ; same for h2.
// GEMM NT: M=16384 rows (r=c*16+b), N=256 (e<128 -> W1, else W2), K=128.
// BM=64, BN=64, BK=16, 256 threads, 4x4 microtile.
__global__ void __launch_bounds__(256) fc_kernel(
    const float* __restrict__ h,
    const float* __restrict__ W1, const float* __restrict__ b1,
    const float* __restrict__ W2, const float* __restrict__ b2)
{
    __shared__ float As[16][64];
    __shared__ float Bs[16][64];
    int t  = threadIdx.x;
    int tx = t & 15, ty = t >> 4;
    int bm = blockIdx.x, bn = blockIdx.y;

    float acc[4][4] = {};

    int ar = t >> 2;            // 0..63
    int kc = (t & 3) << 2;      // 0,4,8,12
    int rowA = bm*64 + ar;
    int e    = bn*64 + ar;
    const float* Bptr = (e < 128) ? (W1 + e*128) : (W2 + (e-128)*128);

    for (int kt = 0; kt < 128; kt += 16) {
        float4 av = *(const float4*)(h + (size_t)rowA*128 + kt + kc);
        float4 bv = *(const float4*)(Bptr + kt + kc);
        As[kc+0][ar]=av.x; As[kc+1][ar]=av.y; As[kc+2][ar]=av.z; As[kc+3][ar]=av.w;
        Bs[kc+0][ar]=bv.x; Bs[kc+1][ar]=bv.y; Bs[kc+2][ar]=bv.z; Bs[kc+3][ar]=bv.w;
        __syncthreads();
#pragma unroll
        for (int k = 0; k < 16; k++) {
            float a[4], bb[4];
#pragma unroll
            for (int i = 0; i < 4; i++) a[i]  = As[k][ty*4+i];
#pragma unroll
            for (int j = 0; j < 4; j++) bb[j] = Bs[k][tx*4+j];
#pragma unroll
            for (int i = 0; i < 4; i++)
#pragma unroll
                for (int j = 0; j < 4; j++)
                    acc[i][j] += a[i]*bb[j];
        }
        __syncthreads();
    }

#pragma unroll
    for (int i = 0; i < 4; i++) {
        int r = bm*64 + ty*4 + i;
        int c = r >> 4, b = r & 15;
#pragma unroll
        for (int j = 0; j < 4; j++) {
            int ee = bn*64 + tx*4 + j;
            float bias = (ee < 128) ? b1[ee] : b2[ee-128];
            float v = acc[i][j] + bias;
            v = v > 0.f ? v : 0.f;
            if (ee < 128) g_h1[((size_t)(b*C + c))*D + ee]       = v;
            else          g_h2[((size_t)(b*C + c))*D + (ee-128)] = v;
        }
    }
}

// ------------------------------------------------- row softmax (axis=2, mask on j)
// dst_sel: 0 -> g_P2 (src=B_t), 1 -> g_Btt (src=B_new)
__global__ void __launch_bounds__(256) softmax_row_kernel(
    const float* __restrict__ src, const int* __restrict__ mask, int dst_sel)
{
    int b = blockIdx.x >> 10;
    int i = blockIdx.x & 1023;
    const float* row = src + ((size_t)b*C + i)*C;
    float* dst = (dst_sel ? g_Btt : g_P2) + ((size_t)b*C + i)*C;
    int t = threadIdx.x;

    float v[4];
    float mx = -3.4e38f;
#pragma unroll
    for (int u = 0; u < 4; u++) {
        int j = u*256 + t;
        float x = (mask[b*C + j] != 0) ? row[j] : NEGV;
        v[u] = x;
        mx = fmaxf(mx, x);
    }
    __shared__ float red[8];
    float w = mx;
#pragma unroll
    for (int o = 16; o > 0; o >>= 1) w = fmaxf(w, __shfl_xor_sync(0xffffffffu, w, o));
    if ((t & 31) == 0) red[t >> 5] = w;
    __syncthreads();
    mx = red[0];
#pragma unroll
    for (int q = 1; q < 8; q++) mx = fmaxf(mx, red[q]);
    __syncthreads();

    float s = 0.f;
#pragma unroll
    for (int u = 0; u < 4; u++) { v[u] = expf(v[u] - mx); s += v[u]; }
#pragma unroll
    for (int o = 16; o > 0; o >>= 1) s += __shfl_xor_sync(0xffffffffu, s, o);
    if ((t & 31) == 0) red[t >> 5] = s;
    __syncthreads();
    float tot = 0.f;
#pragma unroll
    for (int q = 0; q < 8; q++) tot += red[q];
    float inv = 1.0f / tot;
#pragma unroll
    for (int u = 0; u < 4; u++) dst[u*256 + t] = v[u] * inv;
}

// ------------------------------------------------- column softmax (axis=1, mask on i)
// exp without max-subtraction (values are N(0,1)-scale; masked terms are exactly 0),
// mathematically identical to the reference softmax.
__global__ void __launch_bounds__(256) softmax_col_kernel(
    const float* __restrict__ Bt, const int* __restrict__ mask)
{
    int b = blockIdx.y;
    int j = blockIdx.x*256 + threadIdx.x;
    const float* base = Bt  + (size_t)b*C*C + j;
    float*       d    = g_P1 + (size_t)b*C*C + j;
    const int*   mk   = mask + b*C;

    float s = 0.f;
#pragma unroll 8
    for (int i = 0; i < C; i++) {
        float x = base[(size_t)i*C];
        if (mk[i]) s += expf(x);
    }
    float inv = 1.0f / s;
#pragma unroll 8
    for (int i = 0; i < C; i++) {
        float x = base[(size_t)i*C];
        d[(size_t)i*C] = mk[i] ? expf(x)*inv : 0.f;
    }
}

// ---------------------------------------------------------------- B_new GEMM
// B_new[b,i,j] = h1[b,i,:].h2[b,j,:] + gamma * sum_k P2[b,i,k]*P1[b,k,j]; diag=0
// BM=BN=128, BK=8, 256 threads, 8x8 microtile. Writes directly into d_out region.
__global__ void __launch_bounds__(256) bnew_kernel(
    const float* __restrict__ gamma_p, float* __restrict__ out)
{
    int b = blockIdx.z, it = blockIdx.y, jt = blockIdx.x;
    __shared__ float As[8][128];
    __shared__ float Bs[8][128];
    int t = threadIdx.x, tx = t & 15, ty = t >> 4;
    float acc[8][8] = {};

    const float* A  = g_P2 + (size_t)b*C*C + (size_t)(it*128)*C;   // [i][k]
    const float* Bm = g_P1 + (size_t)b*C*C + jt*128;               // [k][j]

    int ar = t >> 1, kc = (t & 1) << 2;     // A loader: row 0..127, k-offset 0/4
    int bk = t >> 5, jc = (t & 31) << 2;    // B loader: k 0..7, j-offset

    for (int kt = 0; kt < C; kt += 8) {
        float4 av = *(const float4*)(A + (size_t)ar*C + kt + kc);
        float4 bv = *(const float4*)(Bm + (size_t)(kt + bk)*C + jc);
        As[kc+0][ar]=av.x; As[kc+1][ar]=av.y; As[kc+2][ar]=av.z; As[kc+3][ar]=av.w;
        *(float4*)&Bs[bk][jc] = bv;
        __syncthreads();
#pragma unroll
        for (int k = 0; k < 8; k++) {
            float a[8], bb[8];
            *(float4*)(a)    = *(const float4*)&As[k][ty*8];
            *(float4*)(a+4)  = *(const float4*)&As[k][ty*8+4];
            *(float4*)(bb)   = *(const float4*)&Bs[k][tx*8];
            *(float4*)(bb+4) = *(const float4*)&Bs[k][tx*8+4];
#pragma unroll
            for (int i = 0; i < 8; i++)
#pragma unroll
                for (int j = 0; j < 8; j++)
                    acc[i][j] += a[i]*bb[j];
        }
        __syncthreads();
    }

    float g = *gamma_p;
#pragma unroll
    for (int i = 0; i < 8; i++)
#pragma unroll
        for (int j = 0; j < 8; j++)
            acc[i][j] *= g;

    // + B_0 = h1 . h2^T  (K=128, both K-contiguous -> NT)
    const float* A2 = g_h1 + ((size_t)b*C + it*128)*D;
    const float* B2 = g_h2 + ((size_t)b*C + jt*128)*D;
    for (int kt = 0; kt < D; kt += 8) {
        float4 av = *(const float4*)(A2 + (size_t)ar*D + kt + kc);
        float4 bv = *(const float4*)(B2 + (size_t)ar*D + kt + kc);
        As[kc+0][ar]=av.x; As[kc+1][ar]=av.y; As[kc+2][ar]=av.z; As[kc+3][ar]=av.w;
        Bs[kc+0][ar]=bv.x; Bs[kc+1][ar]=bv.y; Bs[kc+2][ar]=bv.z; Bs[kc+3][ar]=bv.w;
        __syncthreads();
#pragma unroll
        for (int k = 0; k < 8; k++) {
            float a[8], bb[8];
            *(float4*)(a)    = *(const float4*)&As[k][ty*8];
            *(float4*)(a+4)  = *(const float4*)&As[k][ty*8+4];
            *(float4*)(bb)   = *(const float4*)&Bs[k][tx*8];
            *(float4*)(bb+4) = *(const float4*)&Bs[k][tx*8+4];
#pragma unroll
            for (int i = 0; i < 8; i++)
#pragma unroll
                for (int j = 0; j < 8; j++)
                    acc[i][j] += a[i]*bb[j];
        }
        __syncthreads();
    }

#pragma unroll
    for (int i = 0; i < 8; i++) {
        int gi = it*128 + ty*8 + i;
#pragma unroll
        for (int j = 0; j < 8; j++) {
            int gj = jt*128 + tx*8 + j;
            out[(size_t)b*C*C + (size_t)gi*C + gj] = (gi == gj) ? 0.f : acc[i][j];
        }
    }
}

// ---------------------------------------------------------------- h_tmp GEMM
// h_tmp[c=i,b,d] = sum_j Btt[b,i,j] * h[j,b,d].  BM=128(i), BN=128(d), BK=8.
__global__ void __launch_bounds__(256) htmp_kernel(const float* __restrict__ h)
{
    int b = blockIdx.y, it = blockIdx.x;
    __shared__ float As[8][128];
    __shared__ float Bs[8][128];
    int t = threadIdx.x, tx = t & 15, ty = t >> 4;
    float acc[8][8] = {};

    const float* A = g_Btt + (size_t)b*C*C + (size_t)(it*128)*C;  // [i][j]
    int ar = t >> 1, kc = (t & 1) << 2;
    int bk = t >> 5, dc = (t & 31) << 2;

    for (int kt = 0; kt < C; kt += 8) {
        float4 av = *(const float4*)(A + (size_t)ar*C + kt + kc);
        float4 bv = *(const float4*)(h + (size_t)((kt + bk)*16 + b)*128 + dc);
        As[kc+0][ar]=av.x; As[kc+1][ar]=av.y; As[kc+2][ar]=av.z; As[kc+3][ar]=av.w;
        *(float4*)&Bs[bk][dc] = bv;
        __syncthreads();
#pragma unroll
        for (int k = 0; k < 8; k++) {
            float a[8], bb[8];
            *(float4*)(a)    = *(const float4*)&As[k][ty*8];
            *(float4*)(a+4)  = *(const float4*)&As[k][ty*8+4];
            *(float4*)(bb)   = *(const float4*)&Bs[k][tx*8];
            *(float4*)(bb+4) = *(const float4*)&Bs[k][tx*8+4];
#pragma unroll
            for (int i = 0; i < 8; i++)
#pragma unroll
                for (int j = 0; j < 8; j++)
                    acc[i][j] += a[i]*bb[j];
        }
        __syncthreads();
    }

#pragma unroll
    for (int i = 0; i < 8; i++) {
        int ci = it*128 + ty*8 + i;
#pragma unroll
        for (int j = 0; j < 8; j++) {
            int d = tx*8 + j;
            g_htmp[(size_t)(ci*16 + b)*128 + d] = acc[i][j];
        }
    }
}

// ---------------------------------------------------------------- SFU gate GEMM
// m = [h, ht, h*ht, h-ht] (K=512) built on the fly; dual GEMM vs Wr and Wg.
// o = relu(m.Wr[d]) * sigmoid(m.Wg[d]) + (1-sigmoid)*h
// BM=64 rows, BN=64 d, BK=16, 256 threads, 4x4 microtile, 2 accumulators.
__global__ void __launch_bounds__(256) gate_kernel(
    const float* __restrict__ h,
    const float* __restrict__ Wr, const float* __restrict__ Wg,
    float* __restrict__ o)
{
    __shared__ float As[16][64];
    __shared__ float Br[16][64];
    __shared__ float Bg[16][64];
    int t = threadIdx.x, tx = t & 15, ty = t >> 4;
    int bm = blockIdx.x, bn = blockIdx.y;

    float accr[4][4] = {}, accg[4][4] = {};
    int ar = t >> 2, kc = (t & 3) << 2;
    int rowA = bm*64 + ar;
    int dr = bn*64 + ar;

    for (int kt = 0; kt < 512; kt += 16) {
        int k = kt + kc;
        int seg = k >> 7;      // uniform across the float4 (16 | 128)
        int k0  = k & 127;
        float4 mv;
        if (seg == 0) {
            mv = *(const float4*)(h + (size_t)rowA*128 + k0);
        } else if (seg == 1) {
            mv = *(const float4*)(g_htmp + (size_t)rowA*128 + k0);
        } else {
            float4 hv = *(const float4*)(h      + (size_t)rowA*128 + k0);
            float4 tv = *(const float4*)(g_htmp + (size_t)rowA*128 + k0);
            if (seg == 2) { mv.x=hv.x*tv.x; mv.y=hv.y*tv.y; mv.z=hv.z*tv.z; mv.w=hv.w*tv.w; }
            else          { mv.x=hv.x-tv.x; mv.y=hv.y-tv.y; mv.z=hv.z-tv.z; mv.w=hv.w-tv.w; }
        }
        As[kc+0][ar]=mv.x; As[kc+1][ar]=mv.y; As[kc+2][ar]=mv.z; As[kc+3][ar]=mv.w;

        float4 rv = *(const float4*)(Wr + (size_t)dr*512 + kt + kc);
        float4 gv = *(const float4*)(Wg + (size_t)dr*512 + kt + kc);
        Br[kc+0][ar]=rv.x; Br[kc+1][ar]=rv.y; Br[kc+2][ar]=rv.z; Br[kc+3][ar]=rv.w;
        Bg[kc+0][ar]=gv.x; Bg[kc+1][ar]=gv.y; Bg[kc+2][ar]=gv.z; Bg[kc+3][ar]=gv.w;
        __syncthreads();
#pragma unroll
        for (int k2 = 0; k2 < 16; k2++) {
            float a[4], br[4], bg[4];
#pragma unroll
            for (int i = 0; i < 4; i++) a[i]  = As[k2][ty*4+i];
#pragma unroll
            for (int j = 0; j < 4; j++) { br[j] = Br[k2][tx*4+j]; bg[j] = Bg[k2][tx*4+j]; }
#pragma unroll
            for (int i = 0; i < 4; i++)
#pragma unroll
                for (int j = 0; j < 4; j++) {
                    accr[i][j] += a[i]*br[j];
                    accg[i][j] += a[i]*bg[j];
                }
        }
        __syncthreads();
    }

#pragma unroll
    for (int i = 0; i < 4; i++) {
        int r = bm*64 + ty*4 + i;
#pragma unroll
        for (int j = 0; j < 4; j++) {
            int d = bn*64 + tx*4 + j;
            float x  = fmaxf(accr[i][j], 0.f);
            float gg = 1.0f / (1.0f + expf(-accg[i][j]));
            float hv = h[(size_t)r*128 + d];
            o[(size_t)r*128 + d] = x*gg + (1.0f - gg)*hv;
        }
    }
}

// ---------------------------------------------------------------------------
extern "C" void kernel_launch(void* const* d_in, const int* in_sizes, int n_in,
                              void* d_out, int out_size)
{
    const float* h   = (const float*)d_in[0];
    const int*   hm  = (const int*)  d_in[1];
    const float* Bt  = (const float*)d_in[2];
    const float* W1w = (const float*)d_in[3];
    const float* W1b = (const float*)d_in[4];
    const float* W2w = (const float*)d_in[5];
    const float* W2b = (const float*)d_in[6];
    const float* gam = (const float*)d_in[7];
    const float* Wrw = (const float*)d_in[8];
    const float* Wgw = (const float*)d_in[9];

    float* o_out    = (float*)d_out;                       // (c,b,d) = 2,097,152
    float* bnew_out = (float*)d_out + (size_t)CB*D;        // (b,i,j) = 16,777,216

    fc_kernel<<<dim3(CB/64, 4), 256>>>(h, W1w, W1b, W2w, W2b);
    softmax_row_kernel<<<BATCH*C, 256>>>(Bt, hm, /*dst=g_P2*/0);
    softmax_col_kernel<<<dim3(C/256, BATCH), 256>>>(Bt, hm);
    bnew_kernel<<<dim3(C/128, C/128, BATCH), 256>>>(gam, bnew_out);
    softmax_row_kernel<<<BATCH*C, 256>>>(bnew_out, hm, /*dst=g_Btt*/1);
    htmp_kernel<<<dim3(C/128, BATCH), 256>>>(h);
    gate_kernel<<<dim3(CB/64, 2), 256>>>(h, Wrw, Wgw, o_out);
}

// round 3
// speedup vs baseline: 1.4950x; 1.4950x over previous
#include <cuda_runtime.h>
#include <cuda_bf16.h>
#include <math.h>
#include <cstdint>

#define C 1024
#define BATCH 16
#define D 128
#define CB (C*BATCH)
#define CC (C*C)
#define NEGV (-1e30f)

// ---------------- scratch (static device memory, no runtime allocation) ----
__device__ float g_P1[BATCH*CC];            // col-softmax of masked B_t (fp32, [b][k][j])
__device__ float g_Btt[BATCH*CC];           // row-softmax of masked B_new (fp32)
__device__ float g_htmp[CB*D];              // (c,b,d) layout, row r=c*16+b
__device__ __nv_bfloat16 g_P2hi[BATCH*CC];  // row-softmax of B_t, hi part [b][i][k]
__device__ __nv_bfloat16 g_P2lo[BATCH*CC];
__device__ __nv_bfloat16 g_P1Thi[BATCH*CC]; // transposed col-softmax [b][j][k]
__device__ __nv_bfloat16 g_P1Tlo[BATCH*CC];
__device__ __nv_bfloat16 g_h1hi[CB*D];      // [b][c][d]
__device__ __nv_bfloat16 g_h1lo[CB*D];
__device__ __nv_bfloat16 g_h2hi[CB*D];
__device__ __nv_bfloat16 g_h2lo[CB*D];

// ----------------------------------------------------------------- mma.sync
__device__ __forceinline__ void mma16816(float* c, const uint32_t* a, const uint32_t* b) {
    asm volatile(
        "mma.sync.aligned.m16n8k16.row.col.f32.bf16.bf16.f32 "
        "{%0,%1,%2,%3}, {%4,%5,%6,%7}, {%8,%9}, {%0,%1,%2,%3};"
        : "+f"(c[0]), "+f"(c[1]), "+f"(c[2]), "+f"(c[3])
        : "r"(a[0]), "r"(a[1]), "r"(a[2]), "r"(a[3]), "r"(b[0]), "r"(b[1]));
}

// ---------------------------------------------------------------- FC kernel
// h1[b,c,e] = relu(h[c,b,:].W1[e,:] + b1[e]); outputs written as bf16 hi/lo.
__global__ void __launch_bounds__(256) fc_kernel(
    const float* __restrict__ h,
    const float* __restrict__ W1, const float* __restrict__ b1,
    const float* __restrict__ W2, const float* __restrict__ b2)
{
    __shared__ float As[16][64];
    __shared__ float Bs[16][64];
    int t  = threadIdx.x;
    int tx = t & 15, ty = t >> 4;
    int bm = blockIdx.x, bn = blockIdx.y;

    float acc[4][4] = {};
    int ar = t >> 2;
    int kc = (t & 3) << 2;
    int rowA = bm*64 + ar;
    int e    = bn*64 + ar;
    const float* Bptr = (e < 128) ? (W1 + e*128) : (W2 + (e-128)*128);

    for (int kt = 0; kt < 128; kt += 16) {
        float4 av = *(const float4*)(h + (size_t)rowA*128 + kt + kc);
        float4 bv = *(const float4*)(Bptr + kt + kc);
        As[kc+0][ar]=av.x; As[kc+1][ar]=av.y; As[kc+2][ar]=av.z; As[kc+3][ar]=av.w;
        Bs[kc+0][ar]=bv.x; Bs[kc+1][ar]=bv.y; Bs[kc+2][ar]=bv.z; Bs[kc+3][ar]=bv.w;
        __syncthreads();
#pragma unroll
        for (int k = 0; k < 16; k++) {
            float a[4], bb[4];
#pragma unroll
            for (int i = 0; i < 4; i++) a[i]  = As[k][ty*4+i];
#pragma unroll
            for (int j = 0; j < 4; j++) bb[j] = Bs[k][tx*4+j];
#pragma unroll
            for (int i = 0; i < 4; i++)
#pragma unroll
                for (int j = 0; j < 4; j++)
                    acc[i][j] += a[i]*bb[j];
        }
        __syncthreads();
    }

#pragma unroll
    for (int i = 0; i < 4; i++) {
        int r = bm*64 + ty*4 + i;
        int c = r >> 4, b = r & 15;
#pragma unroll
        for (int j = 0; j < 4; j++) {
            int ee = bn*64 + tx*4 + j;
            float bias = (ee < 128) ? b1[ee] : b2[ee-128];
            float v = acc[i][j] + bias;
            v = v > 0.f ? v : 0.f;
            __nv_bfloat16 hi = __float2bfloat16(v);
            __nv_bfloat16 lo = __float2bfloat16(v - __bfloat162float(hi));
            size_t idx = ((size_t)(b*C + c))*D + (ee & 127);
            if (ee < 128) { g_h1hi[idx] = hi; g_h1lo[idx] = lo; }
            else          { g_h2hi[idx] = hi; g_h2lo[idx] = lo; }
        }
    }
}

// ------------------------------------------------- row softmax (axis=2, mask on j)
// dst_sel 0: write bf16 hi/lo to g_P2hi/lo (src=B_t). dst_sel 1: write fp32 g_Btt.
__global__ void __launch_bounds__(256) softmax_row_kernel(
    const float* __restrict__ src, const int* __restrict__ mask, int dst_sel)
{
    int b = blockIdx.x >> 10;
    int i = blockIdx.x & 1023;
    const float* row = src + ((size_t)b*C + i)*C;
    int t = threadIdx.x;

    float v[4];
    float mx = -3.4e38f;
#pragma unroll
    for (int u = 0; u < 4; u++) {
        int j = u*256 + t;
        float x = (mask[b*C + j] != 0) ? row[j] : NEGV;
        v[u] = x;
        mx = fmaxf(mx, x);
    }
    __shared__ float red[8];
    float w = mx;
#pragma unroll
    for (int o = 16; o > 0; o >>= 1) w = fmaxf(w, __shfl_xor_sync(0xffffffffu, w, o));
    if ((t & 31) == 0) red[t >> 5] = w;
    __syncthreads();
    mx = red[0];
#pragma unroll
    for (int q = 1; q < 8; q++) mx = fmaxf(mx, red[q]);
    __syncthreads();

    float s = 0.f;
#pragma unroll
    for (int u = 0; u < 4; u++) { v[u] = expf(v[u] - mx); s += v[u]; }
#pragma unroll
    for (int o = 16; o > 0; o >>= 1) s += __shfl_xor_sync(0xffffffffu, s, o);
    if ((t & 31) == 0) red[t >> 5] = s;
    __syncthreads();
    float tot = 0.f;
#pragma unroll
    for (int q = 0; q < 8; q++) tot += red[q];
    float inv = 1.0f / tot;

    size_t base = ((size_t)b*C + i)*C;
    if (dst_sel) {
#pragma unroll
        for (int u = 0; u < 4; u++) g_Btt[base + u*256 + t] = v[u] * inv;
    } else {
#pragma unroll
        for (int u = 0; u < 4; u++) {
            float pv = v[u] * inv;
            __nv_bfloat16 hi = __float2bfloat16(pv);
            g_P2hi[base + u*256 + t] = hi;
            g_P2lo[base + u*256 + t] = __float2bfloat16(pv - __bfloat162float(hi));
        }
    }
}

// ------------------------------------------------- column softmax (axis=1, mask on i)
__global__ void __launch_bounds__(256) softmax_col_kernel(
    const float* __restrict__ Bt, const int* __restrict__ mask)
{
    int b = blockIdx.y;
    int j = blockIdx.x*256 + threadIdx.x;
    const float* base = Bt   + (size_t)b*CC + j;
    float*       d    = g_P1 + (size_t)b*CC + j;
    const int*   mk   = mask + b*C;

    float s = 0.f;
#pragma unroll 4
    for (int i = 0; i < C; i++) {
        float e = mk[i] ? expf(base[(size_t)i*C]) : 0.f;
        d[(size_t)i*C] = e;
        s += e;
    }
    float inv = 1.0f / s;
#pragma unroll 4
    for (int i = 0; i < C; i++)
        d[(size_t)i*C] *= inv;
}

// ------------------------------------ transpose + bf16 hi/lo convert of P1 -------
__global__ void __launch_bounds__(256) transpose_conv_kernel()
{
    __shared__ float tile[32][33];
    int b  = blockIdx.z;
    int k0 = blockIdx.y * 32;
    int j0 = blockIdx.x * 32;
    int tx = threadIdx.x & 31, ty = threadIdx.x >> 5;

    const float* src = g_P1 + (size_t)b*CC;
#pragma unroll
    for (int r = ty; r < 32; r += 8)
        tile[r][tx] = src[(size_t)(k0 + r)*C + j0 + tx];
    __syncthreads();
#pragma unroll
    for (int r = ty; r < 32; r += 8) {
        float x = tile[tx][r];
        __nv_bfloat16 hi = __float2bfloat16(x);
        __nv_bfloat16 lo = __float2bfloat16(x - __bfloat162float(hi));
        size_t o = (size_t)b*CC + (size_t)(j0 + r)*C + k0 + tx;
        g_P1Thi[o] = hi;
        g_P1Tlo[o] = lo;
    }
}

// ============================ B_new tensor-core GEMM (mma.sync) =============
// Per CTA (b, it, jt): 128x128 tile of B_new.
//   acc  = P2[b,i,:] . P1T[b,j,:]^T   (K=1024, 16 chunks of 64)
//   acc *= gamma
//   acc += h1[b,i,:] . h2[b,j,:]^T    (K=128, 2 chunks of 64)
// bf16 split precision: hi*hi + hi*lo + lo*hi. Diagonal zeroed on store.
// 8 warps in 2(m) x 4(n); warp tile 64x32 via m16n8k16 (4x4 frags).
#define LDK 72   // padded SMEM row length (bf16 elems) -> conflict-free frag loads
__global__ void __launch_bounds__(256) bnew_mma_kernel(
    const float* __restrict__ gamma_p, float* __restrict__ out)
{
    extern __shared__ __nv_bfloat16 sm[];   // 4 tiles of 128 x LDK bf16
    __nv_bfloat16* sAh = sm;
    __nv_bfloat16* sAl = sm + 128*LDK;
    __nv_bfloat16* sBh = sm + 2*128*LDK;
    __nv_bfloat16* sBl = sm + 3*128*LDK;

    int tid = threadIdx.x, wid = tid >> 5, lid = tid & 31;
    int b = blockIdx.z, it = blockIdx.y, jt = blockIdx.x;
    int wm = wid & 1, wn = wid >> 1;

    float acc[4][4][4] = {};
    float gma = gamma_p[0];

    int lrow = lid >> 2;          // 0..7
    int lcol2 = (lid & 3) << 1;   // 0,2,4,6

    for (int c = 0; c < 18; c++) {
        const __nv_bfloat16 *Ah, *Al, *Bh, *Bl;
        size_t rstride;
        if (c < 16) {
            size_t offA = ((size_t)b*C + (size_t)it*128)*C + (size_t)c*64;
            size_t offB = ((size_t)b*C + (size_t)jt*128)*C + (size_t)c*64;
            Ah = g_P2hi  + offA; Al = g_P2lo  + offA;
            Bh = g_P1Thi + offB; Bl = g_P1Tlo + offB;
            rstride = C;
        } else {
            int cc = c - 16;
            size_t offA = ((size_t)b*C + (size_t)it*128)*D + (size_t)cc*64;
            size_t offB = ((size_t)b*C + (size_t)jt*128)*D + (size_t)cc*64;
            Ah = g_h1hi + offA; Al = g_h1lo + offA;
            Bh = g_h2hi + offB; Bl = g_h2lo + offB;
            rstride = D;
        }

        if (c) __syncthreads();
#pragma unroll
        for (int q = 0; q < 4; q++) {
            int idx = q*256 + tid;
            int row = idx >> 3, seg = idx & 7;
            size_t g = (size_t)row*rstride + seg*8;
            int o = row*LDK + seg*8;
            *(uint4*)(sAh + o) = *(const uint4*)(Ah + g);
            *(uint4*)(sAl + o) = *(const uint4*)(Al + g);
            *(uint4*)(sBh + o) = *(const uint4*)(Bh + g);
            *(uint4*)(sBl + o) = *(const uint4*)(Bl + g);
        }
        __syncthreads();

        // gamma scaling happens right before the first h1.h2 chunk (c==16)
        if (c == 16) {
#pragma unroll
            for (int im = 0; im < 4; im++)
#pragma unroll
                for (int jn = 0; jn < 4; jn++)
#pragma unroll
                    for (int q = 0; q < 4; q++)
                        acc[im][jn][q] *= gma;
        }

#pragma unroll
        for (int ks = 0; ks < 4; ks++) {
            int k0 = ks*16 + lcol2;
            uint32_t ah[4][4], al[4][4];
            int rbase = wm*64 + lrow;
#pragma unroll
            for (int im = 0; im < 4; im++) {
                int r = rbase + im*16;
                ah[im][0] = *(const uint32_t*)(sAh + r*LDK + k0);
                ah[im][1] = *(const uint32_t*)(sAh + (r+8)*LDK + k0);
                ah[im][2] = *(const uint32_t*)(sAh + r*LDK + k0 + 8);
                ah[im][3] = *(const uint32_t*)(sAh + (r+8)*LDK + k0 + 8);
                al[im][0] = *(const uint32_t*)(sAl + r*LDK + k0);
                al[im][1] = *(const uint32_t*)(sAl + (r+8)*LDK + k0);
                al[im][2] = *(const uint32_t*)(sAl + r*LDK + k0 + 8);
                al[im][3] = *(const uint32_t*)(sAl + (r+8)*LDK + k0 + 8);
            }
            uint32_t bh[4][2], bl[4][2];
            int nbase = wn*32 + lrow;
#pragma unroll
            for (int jn = 0; jn < 4; jn++) {
                int n = nbase + jn*8;
                bh[jn][0] = *(const uint32_t*)(sBh + n*LDK + k0);
                bh[jn][1] = *(const uint32_t*)(sBh + n*LDK + k0 + 8);
                bl[jn][0] = *(const uint32_t*)(sBl + n*LDK + k0);
                bl[jn][1] = *(const uint32_t*)(sBl + n*LDK + k0 + 8);
            }
#pragma unroll
            for (int im = 0; im < 4; im++)
#pragma unroll
                for (int jn = 0; jn < 4; jn++) {
                    mma16816(acc[im][jn], ah[im], bh[jn]);
                    mma16816(acc[im][jn], ah[im], bl[jn]);
                    mma16816(acc[im][jn], al[im], bh[jn]);
                }
        }
    }

    // ---- epilogue: zero diagonal, store fp32 ----
    int gi0 = it*128 + wm*64 + lrow;
    int gj0 = jt*128 + wn*32 + lcol2;
    float* obase = out + (size_t)b*CC;
#pragma unroll
    for (int im = 0; im < 4; im++) {
        int r = gi0 + im*16;
#pragma unroll
        for (int jn = 0; jn < 4; jn++) {
            int cj = gj0 + jn*8;
            float2 v0 = make_float2(acc[im][jn][0], acc[im][jn][1]);
            float2 v1 = make_float2(acc[im][jn][2], acc[im][jn][3]);
            if (r == cj)       v0.x = 0.f;
            else if (r == cj+1) v0.y = 0.f;
            if (r+8 == cj)      v1.x = 0.f;
            else if (r+8 == cj+1) v1.y = 0.f;
            *(float2*)(obase + (size_t)r*C + cj)     = v0;
            *(float2*)(obase + (size_t)(r+8)*C + cj) = v1;
        }
    }
}

// ---------------------------------------------------------------- h_tmp GEMM
__global__ void __launch_bounds__(256) htmp_kernel(const float* __restrict__ h)
{
    int b = blockIdx.y, it = blockIdx.x;
    __shared__ float As[8][128];
    __shared__ float Bs[8][128];
    int t = threadIdx.x, tx = t & 15, ty = t >> 4;
    float acc[8][8] = {};

    const float* A = g_Btt + (size_t)b*CC + (size_t)(it*128)*C;
    int ar = t >> 1, kc = (t & 1) << 2;
    int bk = t >> 5, dc = (t & 31) << 2;

    for (int kt = 0; kt < C; kt += 8) {
        float4 av = *(const float4*)(A + (size_t)ar*C + kt + kc);
        float4 bv = *(const float4*)(h + (size_t)((kt + bk)*16 + b)*128 + dc);
        As[kc+0][ar]=av.x; As[kc+1][ar]=av.y; As[kc+2][ar]=av.z; As[kc+3][ar]=av.w;
        *(float4*)&Bs[bk][dc] = bv;
        __syncthreads();
#pragma unroll
        for (int k = 0; k < 8; k++) {
            float a[8], bb[8];
            *(float4*)(a)    = *(const float4*)&As[k][ty*8];
            *(float4*)(a+4)  = *(const float4*)&As[k][ty*8+4];
            *(float4*)(bb)   = *(const float4*)&Bs[k][tx*8];
            *(float4*)(bb+4) = *(const float4*)&Bs[k][tx*8+4];
#pragma unroll
            for (int i = 0; i < 8; i++)
#pragma unroll
                for (int j = 0; j < 8; j++)
                    acc[i][j] += a[i]*bb[j];
        }
        __syncthreads();
    }

#pragma unroll
    for (int i = 0; i < 8; i++) {
        int ci = it*128 + ty*8 + i;
#pragma unroll
        for (int j = 0; j < 8; j++) {
            int d = tx*8 + j;
            g_htmp[(size_t)(ci*16 + b)*128 + d] = acc[i][j];
        }
    }
}

// ---------------------------------------------------------------- SFU gate GEMM
__global__ void __launch_bounds__(256) gate_kernel(
    const float* __restrict__ h,
    const float* __restrict__ Wr, const float* __restrict__ Wg,
    float* __restrict__ o)
{
    __shared__ float As[16][64];
    __shared__ float Br[16][64];
    __shared__ float Bg[16][64];
    int t = threadIdx.x, tx = t & 15, ty = t >> 4;
    int bm = blockIdx.x, bn = blockIdx.y;

    float accr[4][4] = {}, accg[4][4] = {};
    int ar = t >> 2, kc = (t & 3) << 2;
    int rowA = bm*64 + ar;
    int dr = bn*64 + ar;

    for (int kt = 0; kt < 512; kt += 16) {
        int k = kt + kc;
        int seg = k >> 7;
        int k0  = k & 127;
        float4 mv;
        if (seg == 0) {
            mv = *(const float4*)(h + (size_t)rowA*128 + k0);
        } else if (seg == 1) {
            mv = *(const float4*)(g_htmp + (size_t)rowA*128 + k0);
        } else {
            float4 hv = *(const float4*)(h      + (size_t)rowA*128 + k0);
            float4 tv = *(const float4*)(g_htmp + (size_t)rowA*128 + k0);
            if (seg == 2) { mv.x=hv.x*tv.x; mv.y=hv.y*tv.y; mv.z=hv.z*tv.z; mv.w=hv.w*tv.w; }
            else          { mv.x=hv.x-tv.x; mv.y=hv.y-tv.y; mv.z=hv.z-tv.z; mv.w=hv.w-tv.w; }
        }
        As[kc+0][ar]=mv.x; As[kc+1][ar]=mv.y; As[kc+2][ar]=mv.z; As[kc+3][ar]=mv.w;

        float4 rv = *(const float4*)(Wr + (size_t)dr*512 + kt + kc);
        float4 gv = *(const float4*)(Wg + (size_t)dr*512 + kt + kc);
        Br[kc+0][ar]=rv.x; Br[kc+1][ar]=rv.y; Br[kc+2][ar]=rv.z; Br[kc+3][ar]=rv.w;
        Bg[kc+0][ar]=gv.x; Bg[kc+1][ar]=gv.y; Bg[kc+2][ar]=gv.z; Bg[kc+3][ar]=gv.w;
        __syncthreads();
#pragma unroll
        for (int k2 = 0; k2 < 16; k2++) {
            float a[4], br[4], bg[4];
#pragma unroll
            for (int i = 0; i < 4; i++) a[i]  = As[k2][ty*4+i];
#pragma unroll
            for (int j = 0; j < 4; j++) { br[j] = Br[k2][tx*4+j]; bg[j] = Bg[k2][tx*4+j]; }
#pragma unroll
            for (int i = 0; i < 4; i++)
#pragma unroll
                for (int j = 0; j < 4; j++) {
                    accr[i][j] += a[i]*br[j];
                    accg[i][j] += a[i]*bg[j];
                }
        }
        __syncthreads();
    }

#pragma unroll
    for (int i = 0; i < 4; i++) {
        int r = bm*64 + ty*4 + i;
#pragma unroll
        for (int j = 0; j < 4; j++) {
            int d = bn*64 + tx*4 + j;
            float x  = fmaxf(accr[i][j], 0.f);
            float gg = 1.0f / (1.0f + expf(-accg[i][j]));
            float hv = h[(size_t)r*128 + d];
            o[(size_t)r*128 + d] = x*gg + (1.0f - gg)*hv;
        }
    }
}

// ---------------------------------------------------------------------------
extern "C" void kernel_launch(void* const* d_in, const int* in_sizes, int n_in,
                              void* d_out, int out_size)
{
    const float* h   = (const float*)d_in[0];
    const int*   hm  = (const int*)  d_in[1];
    const float* Bt  = (const float*)d_in[2];
    const float* W1w = (const float*)d_in[3];
    const float* W1b = (const float*)d_in[4];
    const float* W2w = (const float*)d_in[5];
    const float* W2b = (const float*)d_in[6];
    const float* gam = (const float*)d_in[7];
    const float* Wrw = (const float*)d_in[8];
    const float* Wgw = (const float*)d_in[9];

    float* o_out    = (float*)d_out;                 // (c,b,d)
    float* bnew_out = (float*)d_out + (size_t)CB*D;  // (b,i,j)

    const int BNEW_SMEM = 4 * 128 * LDK * 2;   // 73728 bytes
    cudaFuncSetAttribute(bnew_mma_kernel,
                         cudaFuncAttributeMaxDynamicSharedMemorySize, BNEW_SMEM);

    fc_kernel<<<dim3(CB/64, 4), 256>>>(h, W1w, W1b, W2w, W2b);
    softmax_row_kernel<<<BATCH*C, 256>>>(Bt, hm, /*->P2 bf16*/0);
    softmax_col_kernel<<<dim3(C/256, BATCH), 256>>>(Bt, hm);
    transpose_conv_kernel<<<dim3(32, 32, BATCH), 256>>>();
    bnew_mma_kernel<<<dim3(C/128, C/128, BATCH), 256, BNEW_SMEM>>>(gam, bnew_out);
    softmax_row_kernel<<<BATCH*C, 256>>>(bnew_out, hm, /*->Btt fp32*/1);
    htmp_kernel<<<dim3(C/128, BATCH), 256>>>(h);
    gate_kernel<<<dim3(CB/64, 2), 256>>>(h, Wrw, Wgw, o_out);
}

// round 4
// speedup vs baseline: 2.0112x; 1.3452x over previous
#include <cuda_runtime.h>
#include <cuda_bf16.h>
#include <math.h>
#include <cstdint>

#define C 1024
#define BATCH 16
#define D 128
#define CB (C*BATCH)
#define CC (C*C)
#define NEGV (-1e30f)

#define LDK 72                     // padded SMEM row (bf16 elems)
#define TILE_E (128*LDK)           // elems per tile
#define TILE_B (TILE_E*2)          // bytes per tile (18432)
#define BUF_B  (4*TILE_B)          // bytes per buffer (4 tiles)

// ---------------- scratch (static device memory, no runtime allocation) ----
__device__ float g_P1[BATCH*CC];             // col-softmax of masked B_t (fp32 [b][k][j])
__device__ __nv_bfloat16 g_P2hi[BATCH*CC];   // row-softmax of B_t [b][i][k]
__device__ __nv_bfloat16 g_P2lo[BATCH*CC];
__device__ __nv_bfloat16 g_P1Thi[BATCH*CC];  // transposed col-softmax [b][j][k]
__device__ __nv_bfloat16 g_P1Tlo[BATCH*CC];
__device__ __nv_bfloat16 g_Btthi[BATCH*CC];  // row-softmax of B_new [b][i][j]
__device__ __nv_bfloat16 g_Bttlo[BATCH*CC];
__device__ __nv_bfloat16 g_h1hi[CB*D];       // [b][c][d]
__device__ __nv_bfloat16 g_h1lo[CB*D];
__device__ __nv_bfloat16 g_h2hi[CB*D];
__device__ __nv_bfloat16 g_h2lo[CB*D];
__device__ __nv_bfloat16 g_hThi[BATCH*D*C];  // [b][d][c]
__device__ __nv_bfloat16 g_hTlo[BATCH*D*C];
__device__ __nv_bfloat16 g_mhi[(size_t)CB*512]; // m = [h, ht, h*ht, h-ht] per row
__device__ __nv_bfloat16 g_mlo[(size_t)CB*512];
__device__ __nv_bfloat16 g_Whi[256*512];     // stacked [Wr; Wg]
__device__ __nv_bfloat16 g_Wlo[256*512];
__device__ float g_z[(size_t)CB*256];        // gate pre-activations

// ----------------------------------------------------------------- helpers
__device__ __forceinline__ uint32_t smem_u32(const void* p) {
    uint32_t a;
    asm("{ .reg .u64 t; cvta.to.shared.u64 t, %1; cvt.u32.u64 %0, t; }" : "=r"(a) : "l"(p));
    return a;
}
__device__ __forceinline__ void mma16816(float* c, const uint32_t* a, const uint32_t* b) {
    asm volatile(
        "mma.sync.aligned.m16n8k16.row.col.f32.bf16.bf16.f32 "
        "{%0,%1,%2,%3}, {%4,%5,%6,%7}, {%8,%9}, {%0,%1,%2,%3};"
        : "+f"(c[0]), "+f"(c[1]), "+f"(c[2]), "+f"(c[3])
        : "r"(a[0]), "r"(a[1]), "r"(a[2]), "r"(a[3]), "r"(b[0]), "r"(b[1]));
}
__device__ __forceinline__ void cp16(uint32_t s, const void* g) {
    asm volatile("cp.async.ca.shared.global [%0], [%1], 16;" :: "r"(s), "l"(g));
}
#define CP_COMMIT() asm volatile("cp.async.commit_group;" ::: "memory")
#define CP_WAIT1()  asm volatile("cp.async.wait_group 1;" ::: "memory")
#define CP_WAIT0()  asm volatile("cp.async.wait_group 0;" ::: "memory")

__device__ __forceinline__ void split2(float2 v, __nv_bfloat162& hi, __nv_bfloat162& lo) {
    hi.x = __float2bfloat16(v.x); lo.x = __float2bfloat16(v.x - __bfloat162float(hi.x));
    hi.y = __float2bfloat16(v.y); lo.y = __float2bfloat16(v.y - __bfloat162float(hi.y));
}

// issue one 4-tile chunk load (Ah, Al, Bh, Bl), 128 rows x 64 bf16 each
__device__ __forceinline__ void issue_tiles(
    uint32_t sb, int tid,
    const __nv_bfloat16* Ah, const __nv_bfloat16* Al,
    const __nv_bfloat16* Bh, const __nv_bfloat16* Bl,
    size_t rsA, size_t rsB)
{
#pragma unroll
    for (int q = 0; q < 4; q++) {
        int idx = q*256 + tid;
        int row = idx >> 3, seg = idx & 7;
        size_t gA = (size_t)row*rsA + seg*8;
        size_t gB = (size_t)row*rsB + seg*8;
        uint32_t so = row*(LDK*2) + seg*16;
        cp16(sb +            so, Ah + gA);
        cp16(sb +   TILE_B + so, Al + gA);
        cp16(sb + 2*TILE_B + so, Bh + gB);
        cp16(sb + 3*TILE_B + so, Bl + gB);
    }
}

// split-bf16 compute of one chunk: acc += A.B^T (hi.hi + hi.lo + lo.hi)
// 8 warps, 2(m) x 4(n); warp tile 64x32 via m16n8k16
__device__ __forceinline__ void compute_chunk(
    const __nv_bfloat16* base, float acc[4][4][4], int wm, int wn, int lid)
{
    const __nv_bfloat16* sAh = base;
    const __nv_bfloat16* sAl = base + TILE_E;
    const __nv_bfloat16* sBh = base + 2*TILE_E;
    const __nv_bfloat16* sBl = base + 3*TILE_E;
    int lrow = lid >> 2;
    int lcol2 = (lid & 3) << 1;
#pragma unroll
    for (int ks = 0; ks < 4; ks++) {
        int k0 = ks*16 + lcol2;
        uint32_t ah[4][4], al[4][4];
        int rbase = wm*64 + lrow;
#pragma unroll
        for (int im = 0; im < 4; im++) {
            int r = rbase + im*16;
            ah[im][0] = *(const uint32_t*)(sAh + r*LDK + k0);
            ah[im][1] = *(const uint32_t*)(sAh + (r+8)*LDK + k0);
            ah[im][2] = *(const uint32_t*)(sAh + r*LDK + k0 + 8);
            ah[im][3] = *(const uint32_t*)(sAh + (r+8)*LDK + k0 + 8);
            al[im][0] = *(const uint32_t*)(sAl + r*LDK + k0);
            al[im][1] = *(const uint32_t*)(sAl + (r+8)*LDK + k0);
            al[im][2] = *(const uint32_t*)(sAl + r*LDK + k0 + 8);
            al[im][3] = *(const uint32_t*)(sAl + (r+8)*LDK + k0 + 8);
        }
        uint32_t bh[4][2], bl[4][2];
        int nbase = wn*32 + lrow;
#pragma unroll
        for (int jn = 0; jn < 4; jn++) {
            int n = nbase + jn*8;
            bh[jn][0] = *(const uint32_t*)(sBh + n*LDK + k0);
            bh[jn][1] = *(const uint32_t*)(sBh + n*LDK + k0 + 8);
            bl[jn][0] = *(const uint32_t*)(sBl + n*LDK + k0);
            bl[jn][1] = *(const uint32_t*)(sBl + n*LDK + k0 + 8);
        }
#pragma unroll
        for (int im = 0; im < 4; im++)
#pragma unroll
            for (int jn = 0; jn < 4; jn++) {
                mma16816(acc[im][jn], ah[im], bh[jn]);
                mma16816(acc[im][jn], ah[im], bl[jn]);
                mma16816(acc[im][jn], al[im], bh[jn]);
            }
    }
}

// ---------------------------------------------------------------- FC kernel
__global__ void __launch_bounds__(256) fc_kernel(
    const float* __restrict__ h,
    const float* __restrict__ W1, const float* __restrict__ b1,
    const float* __restrict__ W2, const float* __restrict__ b2)
{
    __shared__ float As[16][64];
    __shared__ float Bs[16][64];
    int t  = threadIdx.x;
    int tx = t & 15, ty = t >> 4;
    int bm = blockIdx.x, bn = blockIdx.y;

    float acc[4][4] = {};
    int ar = t >> 2;
    int kc = (t & 3) << 2;
    int rowA = bm*64 + ar;
    int e    = bn*64 + ar;
    const float* Bptr = (e < 128) ? (W1 + e*128) : (W2 + (e-128)*128);

    for (int kt = 0; kt < 128; kt += 16) {
        float4 av = *(const float4*)(h + (size_t)rowA*128 + kt + kc);
        float4 bv = *(const float4*)(Bptr + kt + kc);
        As[kc+0][ar]=av.x; As[kc+1][ar]=av.y; As[kc+2][ar]=av.z; As[kc+3][ar]=av.w;
        Bs[kc+0][ar]=bv.x; Bs[kc+1][ar]=bv.y; Bs[kc+2][ar]=bv.z; Bs[kc+3][ar]=bv.w;
        __syncthreads();
#pragma unroll
        for (int k = 0; k < 16; k++) {
            float a[4], bb[4];
#pragma unroll
            for (int i = 0; i < 4; i++) a[i]  = As[k][ty*4+i];
#pragma unroll
            for (int j = 0; j < 4; j++) bb[j] = Bs[k][tx*4+j];
#pragma unroll
            for (int i = 0; i < 4; i++)
#pragma unroll
                for (int j = 0; j < 4; j++)
                    acc[i][j] += a[i]*bb[j];
        }
        __syncthreads();
    }

#pragma unroll
    for (int i = 0; i < 4; i++) {
        int r = bm*64 + ty*4 + i;
        int c = r >> 4, b = r & 15;
#pragma unroll
        for (int j = 0; j < 4; j++) {
            int ee = bn*64 + tx*4 + j;
            float bias = (ee < 128) ? b1[ee] : b2[ee-128];
            float v = acc[i][j] + bias;
            v = v > 0.f ? v : 0.f;
            __nv_bfloat16 hi = __float2bfloat16(v);
            __nv_bfloat16 lo = __float2bfloat16(v - __bfloat162float(hi));
            size_t idx = ((size_t)(b*C + c))*D + (ee & 127);
            if (ee < 128) { g_h1hi[idx] = hi; g_h1lo[idx] = lo; }
            else          { g_h2hi[idx] = hi; g_h2lo[idx] = lo; }
        }
    }
}

// ------------------------------------------------- row softmax (axis=2, mask on j)
// writes bf16 hi/lo: dst_sel 0 -> g_P2 (src=B_t), 1 -> g_Btt (src=B_new)
__global__ void __launch_bounds__(256) softmax_row_kernel(
    const float* __restrict__ src, const int* __restrict__ mask, int dst_sel)
{
    int b = blockIdx.x >> 10;
    int i = blockIdx.x & 1023;
    const float* row = src + ((size_t)b*C + i)*C;
    int t = threadIdx.x;

    float v[4];
    float mx = -3.4e38f;
#pragma unroll
    for (int u = 0; u < 4; u++) {
        int j = u*256 + t;
        float x = (mask[b*C + j] != 0) ? row[j] : NEGV;
        v[u] = x;
        mx = fmaxf(mx, x);
    }
    __shared__ float red[8];
    float w = mx;
#pragma unroll
    for (int o = 16; o > 0; o >>= 1) w = fmaxf(w, __shfl_xor_sync(0xffffffffu, w, o));
    if ((t & 31) == 0) red[t >> 5] = w;
    __syncthreads();
    mx = red[0];
#pragma unroll
    for (int q = 1; q < 8; q++) mx = fmaxf(mx, red[q]);
    __syncthreads();

    float s = 0.f;
#pragma unroll
    for (int u = 0; u < 4; u++) { v[u] = expf(v[u] - mx); s += v[u]; }
#pragma unroll
    for (int o = 16; o > 0; o >>= 1) s += __shfl_xor_sync(0xffffffffu, s, o);
    if ((t & 31) == 0) red[t >> 5] = s;
    __syncthreads();
    float tot = 0.f;
#pragma unroll
    for (int q = 0; q < 8; q++) tot += red[q];
    float inv = 1.0f / tot;

    size_t base = ((size_t)b*C + i)*C;
    __nv_bfloat16* dhi = dst_sel ? g_Btthi : g_P2hi;
    __nv_bfloat16* dlo = dst_sel ? g_Bttlo : g_P2lo;
#pragma unroll
    for (int u = 0; u < 4; u++) {
        float pv = v[u] * inv;
        __nv_bfloat16 hi = __float2bfloat16(pv);
        dhi[base + u*256 + t] = hi;
        dlo[base + u*256 + t] = __float2bfloat16(pv - __bfloat162float(hi));
    }
}

// ------------------------------------------------- column softmax (axis=1, mask on i)
__global__ void __launch_bounds__(256) softmax_col_kernel(
    const float* __restrict__ Bt, const int* __restrict__ mask)
{
    int b = blockIdx.y;
    int j = blockIdx.x*256 + threadIdx.x;
    const float* base = Bt   + (size_t)b*CC + j;
    float*       d    = g_P1 + (size_t)b*CC + j;
    const int*   mk   = mask + b*C;

    float s = 0.f;
#pragma unroll 4
    for (int i = 0; i < C; i++) {
        float e = mk[i] ? expf(base[(size_t)i*C]) : 0.f;
        d[(size_t)i*C] = e;
        s += e;
    }
    float inv = 1.0f / s;
#pragma unroll 4
    for (int i = 0; i < C; i++)
        d[(size_t)i*C] *= inv;
}

// ------------------------------------ transpose + bf16 hi/lo convert of P1 -------
__global__ void __launch_bounds__(256) transpose_conv_kernel()
{
    __shared__ float tile[32][33];
    int b  = blockIdx.z;
    int k0 = blockIdx.y * 32;
    int j0 = blockIdx.x * 32;
    int tx = threadIdx.x & 31, ty = threadIdx.x >> 5;

    const float* src = g_P1 + (size_t)b*CC;
#pragma unroll
    for (int r = ty; r < 32; r += 8)
        tile[r][tx] = src[(size_t)(k0 + r)*C + j0 + tx];
    __syncthreads();
#pragma unroll
    for (int r = ty; r < 32; r += 8) {
        float x = tile[tx][r];
        __nv_bfloat16 hi = __float2bfloat16(x);
        __nv_bfloat16 lo = __float2bfloat16(x - __bfloat162float(hi));
        size_t o = (size_t)b*CC + (size_t)(j0 + r)*C + k0 + tx;
        g_P1Thi[o] = hi;
        g_P1Tlo[o] = lo;
    }
}

// ------------------------------------ hT transpose: h(c,b,d) -> [b][d][c] hi/lo
__global__ void __launch_bounds__(256) ht_transpose_kernel(const float* __restrict__ h)
{
    __shared__ float tile[32][33];
    int b  = blockIdx.z;
    int c0 = blockIdx.x * 32;
    int d0 = blockIdx.y * 32;
    int tx = threadIdx.x & 31, ty = threadIdx.x >> 5;

#pragma unroll
    for (int r = ty; r < 32; r += 8)
        tile[r][tx] = h[(size_t)((c0 + r)*16 + b)*128 + d0 + tx];
    __syncthreads();
#pragma unroll
    for (int r = ty; r < 32; r += 8) {
        float x = tile[tx][r];                  // (c = c0+tx, d = d0+r)
        __nv_bfloat16 hi = __float2bfloat16(x);
        __nv_bfloat16 lo = __float2bfloat16(x - __bfloat162float(hi));
        size_t o = (size_t)b*D*C + (size_t)(d0 + r)*C + c0 + tx;
        g_hThi[o] = hi;
        g_hTlo[o] = lo;
    }
}

// ------------------------------------ weight stack + split: [Wr; Wg] -> g_W hi/lo
__global__ void __launch_bounds__(256) wsplit_kernel(
    const float* __restrict__ Wr, const float* __restrict__ Wg)
{
    int idx = blockIdx.x*256 + threadIdx.x;     // 0 .. 256*512-1
    int n = idx >> 9, k = idx & 511;
    float x = (n < 128) ? Wr[n*512 + k] : Wg[(n-128)*512 + k];
    __nv_bfloat16 hi = __float2bfloat16(x);
    g_Whi[idx] = hi;
    g_Wlo[idx] = __float2bfloat16(x - __bfloat162float(hi));
}

// ============================ B_new tensor-core GEMM (pipelined) =============
__global__ void __launch_bounds__(256) bnew_mma_kernel(
    const float* __restrict__ gamma_p, float* __restrict__ out)
{
    extern __shared__ __nv_bfloat16 sm[];
    int tid = threadIdx.x, wid = tid >> 5, lid = tid & 31;
    int b = blockIdx.z, it = blockIdx.y, jt = blockIdx.x;
    int wm = wid & 1, wn = wid >> 1;
    uint32_t sb = smem_u32(sm);

    float acc[4][4][4] = {};
    float gma = gamma_p[0];

    auto issue = [&](int c, int buf) {
        const __nv_bfloat16 *Ah, *Al, *Bh, *Bl;
        size_t rs;
        if (c < 16) {
            size_t offA = ((size_t)b*C + (size_t)it*128)*C + (size_t)c*64;
            size_t offB = ((size_t)b*C + (size_t)jt*128)*C + (size_t)c*64;
            Ah = g_P2hi  + offA; Al = g_P2lo  + offA;
            Bh = g_P1Thi + offB; Bl = g_P1Tlo + offB;
            rs = C;
        } else {
            int cc = c - 16;
            size_t offA = ((size_t)b*C + (size_t)it*128)*D + (size_t)cc*64;
            size_t offB = ((size_t)b*C + (size_t)jt*128)*D + (size_t)cc*64;
            Ah = g_h1hi + offA; Al = g_h1lo + offA;
            Bh = g_h2hi + offB; Bl = g_h2lo + offB;
            rs = D;
        }
        issue_tiles(sb + buf*BUF_B, tid, Ah, Al, Bh, Bl, rs, rs);
    };

    issue(0, 0); CP_COMMIT();
    for (int c = 0; c < 18; c++) {
        if (c + 1 < 18) { issue(c + 1, (c + 1) & 1); CP_COMMIT(); CP_WAIT1(); }
        else CP_WAIT0();
        __syncthreads();
        if (c == 16) {
#pragma unroll
            for (int im = 0; im < 4; im++)
#pragma unroll
                for (int jn = 0; jn < 4; jn++)
#pragma unroll
                    for (int q = 0; q < 4; q++)
                        acc[im][jn][q] *= gma;
        }
        compute_chunk(sm + (c & 1)*4*TILE_E, acc, wm, wn, lid);
        __syncthreads();
    }

    // epilogue: zero diagonal, store fp32
    int lrow = lid >> 2, lcol2 = (lid & 3) << 1;
    int gi0 = it*128 + wm*64 + lrow;
    int gj0 = jt*128 + wn*32 + lcol2;
    float* obase = out + (size_t)b*CC;
#pragma unroll
    for (int im = 0; im < 4; im++) {
        int r = gi0 + im*16;
#pragma unroll
        for (int jn = 0; jn < 4; jn++) {
            int cj = gj0 + jn*8;
            float2 v0 = make_float2(acc[im][jn][0], acc[im][jn][1]);
            float2 v1 = make_float2(acc[im][jn][2], acc[im][jn][3]);
            if (r == cj)        v0.x = 0.f;
            else if (r == cj+1) v0.y = 0.f;
            if (r+8 == cj)      v1.x = 0.f;
            else if (r+8 == cj+1) v1.y = 0.f;
            *(float2*)(obase + (size_t)r*C + cj)     = v0;
            *(float2*)(obase + (size_t)(r+8)*C + cj) = v1;
        }
    }
}

// ============================ h_tmp GEMM + m construction ====================
// per CTA (it, b): h_tmp tile 128(i) x 128(d) = Btt[b,i,:] . hT[b,d,:]^T, K=1024
// epilogue builds m = [h, ht, h*ht, h-ht] rows r = c*16+b, bf16 hi/lo.
__global__ void __launch_bounds__(256) htmp_mma_kernel(const float* __restrict__ h)
{
    extern __shared__ __nv_bfloat16 sm[];
    int tid = threadIdx.x, wid = tid >> 5, lid = tid & 31;
    int it = blockIdx.x, b = blockIdx.y;
    int wm = wid & 1, wn = wid >> 1;
    uint32_t sb = smem_u32(sm);

    float acc[4][4][4] = {};

    auto issue = [&](int c, int buf) {
        size_t offA = ((size_t)b*C + (size_t)it*128)*C + (size_t)c*64;
        size_t offB = (size_t)b*D*C + (size_t)c*64;
        issue_tiles(sb + buf*BUF_B, tid,
                    g_Btthi + offA, g_Bttlo + offA,
                    g_hThi + offB, g_hTlo + offB, C, C);
    };

    issue(0, 0); CP_COMMIT();
    for (int c = 0; c < 16; c++) {
        if (c + 1 < 16) { issue(c + 1, (c + 1) & 1); CP_COMMIT(); CP_WAIT1(); }
        else CP_WAIT0();
        __syncthreads();
        compute_chunk(sm + (c & 1)*4*TILE_E, acc, wm, wn, lid);
        __syncthreads();
    }

    // epilogue: build m rows
    int lrow = lid >> 2, lcol2 = (lid & 3) << 1;
    int ci0 = it*128 + wm*64 + lrow;
    int d0  = wn*32 + lcol2;
#pragma unroll
    for (int im = 0; im < 4; im++) {
#pragma unroll
        for (int half = 0; half < 2; half++) {
            int cg = ci0 + im*16 + half*8;
            int r  = cg*16 + b;
#pragma unroll
            for (int jn = 0; jn < 4; jn++) {
                int dj = d0 + jn*8;
                float2 ht = half ? make_float2(acc[im][jn][2], acc[im][jn][3])
                                 : make_float2(acc[im][jn][0], acc[im][jn][1]);
                float2 hv = *(const float2*)(h + (size_t)r*128 + dj);
                float2 seg[4];
                seg[0] = hv;
                seg[1] = ht;
                seg[2] = make_float2(hv.x*ht.x, hv.y*ht.y);
                seg[3] = make_float2(hv.x-ht.x, hv.y-ht.y);
#pragma unroll
                for (int s = 0; s < 4; s++) {
                    __nv_bfloat162 hi, lo;
                    split2(seg[s], hi, lo);
                    size_t o = (size_t)r*512 + s*128 + dj;
                    *(__nv_bfloat162*)(g_mhi + o) = hi;
                    *(__nv_bfloat162*)(g_mlo + o) = lo;
                }
            }
        }
    }
}

// ============================ gate GEMM: z = m . W^T =========================
// per CTA (bm, half): tile 128 rows x 128 cols of z (half selects Wr vs Wg rows)
__global__ void __launch_bounds__(256) gate_mma_kernel()
{
    extern __shared__ __nv_bfloat16 sm[];
    int tid = threadIdx.x, wid = tid >> 5, lid = tid & 31;
    int bm = blockIdx.x, half = blockIdx.y;
    int wm = wid & 1, wn = wid >> 1;
    uint32_t sb = smem_u32(sm);

    float acc[4][4][4] = {};

    auto issue = [&](int c, int buf) {
        size_t offA = ((size_t)bm*128)*512 + (size_t)c*64;
        size_t offB = ((size_t)half*128)*512 + (size_t)c*64;
        issue_tiles(sb + buf*BUF_B, tid,
                    g_mhi + offA, g_mlo + offA,
                    g_Whi + offB, g_Wlo + offB, 512, 512);
    };

    issue(0, 0); CP_COMMIT();
    for (int c = 0; c < 8; c++) {
        if (c + 1 < 8) { issue(c + 1, (c + 1) & 1); CP_COMMIT(); CP_WAIT1(); }
        else CP_WAIT0();
        __syncthreads();
        compute_chunk(sm + (c & 1)*4*TILE_E, acc, wm, wn, lid);
        __syncthreads();
    }

    int lrow = lid >> 2, lcol2 = (lid & 3) << 1;
    int r0 = bm*128 + wm*64 + lrow;
    int n0 = half*128 + wn*32 + lcol2;
#pragma unroll
    for (int im = 0; im < 4; im++) {
        int r = r0 + im*16;
#pragma unroll
        for (int jn = 0; jn < 4; jn++) {
            int n = n0 + jn*8;
            *(float2*)(g_z + (size_t)r*256 + n)     = make_float2(acc[im][jn][0], acc[im][jn][1]);
            *(float2*)(g_z + (size_t)(r+8)*256 + n) = make_float2(acc[im][jn][2], acc[im][jn][3]);
        }
    }
}

// ------------------------------------------------ combine: o = x*g + (1-g)*h
__global__ void __launch_bounds__(256) combine_kernel(
    const float* __restrict__ h, float* __restrict__ o)
{
    int idx = blockIdx.x*256 + threadIdx.x;     // over CB*128
    int r = idx >> 7, d = idx & 127;
    float zr = g_z[(size_t)r*256 + d];
    float zg = g_z[(size_t)r*256 + 128 + d];
    float x  = fmaxf(zr, 0.f);
    float gg = 1.0f / (1.0f + expf(-zg));
    float hv = h[(size_t)r*128 + d];
    o[(size_t)r*128 + d] = x*gg + (1.0f - gg)*hv;
}

// ---------------------------------------------------------------------------
extern "C" void kernel_launch(void* const* d_in, const int* in_sizes, int n_in,
                              void* d_out, int out_size)
{
    const float* h   = (const float*)d_in[0];
    const int*   hm  = (const int*)  d_in[1];
    const float* Bt  = (const float*)d_in[2];
    const float* W1w = (const float*)d_in[3];
    const float* W1b = (const float*)d_in[4];
    const float* W2w = (const float*)d_in[5];
    const float* W2b = (const float*)d_in[6];
    const float* gam = (const float*)d_in[7];
    const float* Wrw = (const float*)d_in[8];
    const float* Wgw = (const float*)d_in[9];

    float* o_out    = (float*)d_out;                 // (c,b,d)
    float* bnew_out = (float*)d_out + (size_t)CB*D;  // (b,i,j)

    const int MMA_SMEM = 2*BUF_B;   // 147456 bytes
    cudaFuncSetAttribute(bnew_mma_kernel, cudaFuncAttributeMaxDynamicSharedMemorySize, MMA_SMEM);
    cudaFuncSetAttribute(htmp_mma_kernel, cudaFuncAttributeMaxDynamicSharedMemorySize, MMA_SMEM);
    cudaFuncSetAttribute(gate_mma_kernel, cudaFuncAttributeMaxDynamicSharedMemorySize, MMA_SMEM);

    fc_kernel<<<dim3(CB/64, 4), 256>>>(h, W1w, W1b, W2w, W2b);
    ht_transpose_kernel<<<dim3(C/32, D/32, BATCH), 256>>>(h);
    wsplit_kernel<<<512, 256>>>(Wrw, Wgw);
    softmax_row_kernel<<<BATCH*C, 256>>>(Bt, hm, /*->P2*/0);
    softmax_col_kernel<<<dim3(C/256, BATCH), 256>>>(Bt, hm);
    transpose_conv_kernel<<<dim3(32, 32, BATCH), 256>>>();
    bnew_mma_kernel<<<dim3(C/128, C/128, BATCH), 256, MMA_SMEM>>>(gam, bnew_out);
    softmax_row_kernel<<<BATCH*C, 256>>>(bnew_out, hm, /*->Btt*/1);
    htmp_mma_kernel<<<dim3(C/128, BATCH), 256, MMA_SMEM>>>(h);
    gate_mma_kernel<<<dim3(CB/128, 2), 256, MMA_SMEM>>>();
    combine_kernel<<<CB*128/256, 256>>>(h, o_out);
}

// round 5
// speedup vs baseline: 3.8273x; 1.9030x over previous
#include <cuda_runtime.h>
#include <cuda_bf16.h>
#include <math.h>
#include <cstdint>

#define C 1024
#define BATCH 16
#define D 128
#define CB (C*BATCH)
#define CC (C*C)
#define NEGV (-1e30f)

#define LDK 72                     // padded SMEM row (bf16 elems)
#define TILE_E (128*LDK)           // elems per tile
#define TILE_B (TILE_E*2)          // bytes per tile (18432)
#define BUF2_B (2*TILE_B)          // 2-tile buffer bytes (36864)
#define BUF2_E (2*TILE_E)
#define BUF4_B (4*TILE_B)          // 4-tile buffer bytes (73728)

// ---------------- scratch (static device memory, no runtime allocation) ----
__device__ __nv_bfloat16 g_P2hi[BATCH*CC];   // row-softmax of B_t [b][i][k] (hi only)
__device__ __nv_bfloat16 g_EThi[BATCH*CC];   // masked exp of B_t, transposed [b][j][k]
__device__ float g_sum[BATCH*C];             // column sums of masked exp
__device__ __nv_bfloat16 g_Btthi[BATCH*CC];  // row-softmax of B_new [b][i][j]
__device__ __nv_bfloat16 g_Bttlo[BATCH*CC];
__device__ __nv_bfloat16 g_h1hi[CB*D];       // [b][c][d]
__device__ __nv_bfloat16 g_h1lo[CB*D];
__device__ __nv_bfloat16 g_h2hi[CB*D];
__device__ __nv_bfloat16 g_h2lo[CB*D];
__device__ __nv_bfloat16 g_hThi[BATCH*D*C];  // [b][d][c]
__device__ __nv_bfloat16 g_hTlo[BATCH*D*C];
__device__ __nv_bfloat16 g_mhi[(size_t)CB*512]; // m = [h, ht, h*ht, h-ht]
__device__ __nv_bfloat16 g_mlo[(size_t)CB*512];
__device__ __nv_bfloat16 g_Whi[256*512];     // stacked [Wr; Wg]
__device__ __nv_bfloat16 g_Wlo[256*512];
__device__ float g_z[(size_t)CB*256];        // gate pre-activations

// ----------------------------------------------------------------- helpers
__device__ __forceinline__ uint32_t smem_u32(const void* p) {
    uint32_t a;
    asm("{ .reg .u64 t; cvta.to.shared.u64 t, %1; cvt.u32.u64 %0, t; }" : "=r"(a) : "l"(p));
    return a;
}
__device__ __forceinline__ void mma16816(float* c, const uint32_t* a, const uint32_t* b) {
    asm volatile(
        "mma.sync.aligned.m16n8k16.row.col.f32.bf16.bf16.f32 "
        "{%0,%1,%2,%3}, {%4,%5,%6,%7}, {%8,%9}, {%0,%1,%2,%3};"
        : "+f"(c[0]), "+f"(c[1]), "+f"(c[2]), "+f"(c[3])
        : "r"(a[0]), "r"(a[1]), "r"(a[2]), "r"(a[3]), "r"(b[0]), "r"(b[1]));
}
__device__ __forceinline__ void cp16(uint32_t s, const void* g) {
    asm volatile("cp.async.ca.shared.global [%0], [%1], 16;" :: "r"(s), "l"(g));
}
#define CP_COMMIT() asm volatile("cp.async.commit_group;" ::: "memory")
#define CP_WAITN(n) asm volatile("cp.async.wait_group %0;" :: "n"(n) : "memory")

__device__ __forceinline__ void split2(float2 v, __nv_bfloat162& hi, __nv_bfloat162& lo) {
    hi.x = __float2bfloat16(v.x); lo.x = __float2bfloat16(v.x - __bfloat162float(hi.x));
    hi.y = __float2bfloat16(v.y); lo.y = __float2bfloat16(v.y - __bfloat162float(hi.y));
}

// load one 2-tile chunk (A, B), 128 rows x 64 bf16 each
__device__ __forceinline__ void issue_single(
    uint32_t sb, int tid,
    const __nv_bfloat16* A, const __nv_bfloat16* Bp, size_t rs)
{
#pragma unroll
    for (int q = 0; q < 4; q++) {
        int idx = q*256 + tid;
        int row = idx >> 3, seg = idx & 7;
        size_t g = (size_t)row*rs + seg*8;
        uint32_t so = row*(LDK*2) + seg*16;
        cp16(sb +          so, A  + g);
        cp16(sb + TILE_B + so, Bp + g);
    }
}

// load one 4-tile chunk (Ah, Al, Bh, Bl)
__device__ __forceinline__ void issue_tiles(
    uint32_t sb, int tid,
    const __nv_bfloat16* Ah, const __nv_bfloat16* Al,
    const __nv_bfloat16* Bh, const __nv_bfloat16* Bl,
    size_t rsA, size_t rsB)
{
#pragma unroll
    for (int q = 0; q < 4; q++) {
        int idx = q*256 + tid;
        int row = idx >> 3, seg = idx & 7;
        size_t gA = (size_t)row*rsA + seg*8;
        size_t gB = (size_t)row*rsB + seg*8;
        uint32_t so = row*(LDK*2) + seg*16;
        cp16(sb +            so, Ah + gA);
        cp16(sb +   TILE_B + so, Al + gA);
        cp16(sb + 2*TILE_B + so, Bh + gB);
        cp16(sb + 3*TILE_B + so, Bl + gB);
    }
}

// single-precision-term chunk: acc += A.B^T (one mma per tile pair)
__device__ __forceinline__ void compute_chunk1(
    const __nv_bfloat16* base, float acc[4][4][4], int wm, int wn, int lid)
{
    const __nv_bfloat16* sA = base;
    const __nv_bfloat16* sB = base + TILE_E;
    int lrow = lid >> 2;
    int lcol2 = (lid & 3) << 1;
#pragma unroll
    for (int ks = 0; ks < 4; ks++) {
        int k0 = ks*16 + lcol2;
        uint32_t a[4][4];
        int rbase = wm*64 + lrow;
#pragma unroll
        for (int im = 0; im < 4; im++) {
            int r = rbase + im*16;
            a[im][0] = *(const uint32_t*)(sA + r*LDK + k0);
            a[im][1] = *(const uint32_t*)(sA + (r+8)*LDK + k0);
            a[im][2] = *(const uint32_t*)(sA + r*LDK + k0 + 8);
            a[im][3] = *(const uint32_t*)(sA + (r+8)*LDK + k0 + 8);
        }
        uint32_t bb[4][2];
        int nbase = wn*32 + lrow;
#pragma unroll
        for (int jn = 0; jn < 4; jn++) {
            int n = nbase + jn*8;
            bb[jn][0] = *(const uint32_t*)(sB + n*LDK + k0);
            bb[jn][1] = *(const uint32_t*)(sB + n*LDK + k0 + 8);
        }
#pragma unroll
        for (int im = 0; im < 4; im++)
#pragma unroll
            for (int jn = 0; jn < 4; jn++)
                mma16816(acc[im][jn], a[im], bb[jn]);
    }
}

// split-bf16 (3-mma) chunk: acc += A.B^T (hi.hi + hi.lo + lo.hi)
__device__ __forceinline__ void compute_chunk(
    const __nv_bfloat16* base, float acc[4][4][4], int wm, int wn, int lid)
{
    const __nv_bfloat16* sAh = base;
    const __nv_bfloat16* sAl = base + TILE_E;
    const __nv_bfloat16* sBh = base + 2*TILE_E;
    const __nv_bfloat16* sBl = base + 3*TILE_E;
    int lrow = lid >> 2;
    int lcol2 = (lid & 3) << 1;
#pragma unroll
    for (int ks = 0; ks < 4; ks++) {
        int k0 = ks*16 + lcol2;
        uint32_t ah[4][4], al[4][4];
        int rbase = wm*64 + lrow;
#pragma unroll
        for (int im = 0; im < 4; im++) {
            int r = rbase + im*16;
            ah[im][0] = *(const uint32_t*)(sAh + r*LDK + k0);
            ah[im][1] = *(const uint32_t*)(sAh + (r+8)*LDK + k0);
            ah[im][2] = *(const uint32_t*)(sAh + r*LDK + k0 + 8);
            ah[im][3] = *(const uint32_t*)(sAh + (r+8)*LDK + k0 + 8);
            al[im][0] = *(const uint32_t*)(sAl + r*LDK + k0);
            al[im][1] = *(const uint32_t*)(sAl + (r+8)*LDK + k0);
            al[im][2] = *(const uint32_t*)(sAl + r*LDK + k0 + 8);
            al[im][3] = *(const uint32_t*)(sAl + (r+8)*LDK + k0 + 8);
        }
        uint32_t bh[4][2], bl[4][2];
        int nbase = wn*32 + lrow;
#pragma unroll
        for (int jn = 0; jn < 4; jn++) {
            int n = nbase + jn*8;
            bh[jn][0] = *(const uint32_t*)(sBh + n*LDK + k0);
            bh[jn][1] = *(const uint32_t*)(sBh + n*LDK + k0 + 8);
            bl[jn][0] = *(const uint32_t*)(sBl + n*LDK + k0);
            bl[jn][1] = *(const uint32_t*)(sBl + n*LDK + k0 + 8);
        }
#pragma unroll
        for (int im = 0; im < 4; im++)
#pragma unroll
            for (int jn = 0; jn < 4; jn++) {
                mma16816(acc[im][jn], ah[im], bh[jn]);
                mma16816(acc[im][jn], ah[im], bl[jn]);
                mma16816(acc[im][jn], al[im], bh[jn]);
            }
    }
}

// ---------------------------------------------------------------- zero sums
__global__ void __launch_bounds__(256) zero_sum_kernel()
{
    g_sum[blockIdx.x*256 + threadIdx.x] = 0.f;
}

// ---------------------------------------------------------------- FC kernel
__global__ void __launch_bounds__(256) fc_kernel(
    const float* __restrict__ h,
    const float* __restrict__ W1, const float* __restrict__ b1,
    const float* __restrict__ W2, const float* __restrict__ b2)
{
    __shared__ float As[16][64];
    __shared__ float Bs[16][64];
    int t  = threadIdx.x;
    int tx = t & 15, ty = t >> 4;
    int bm = blockIdx.x, bn = blockIdx.y;

    float acc[4][4] = {};
    int ar = t >> 2;
    int kc = (t & 3) << 2;
    int rowA = bm*64 + ar;
    int e    = bn*64 + ar;
    const float* Bptr = (e < 128) ? (W1 + e*128) : (W2 + (e-128)*128);

    for (int kt = 0; kt < 128; kt += 16) {
        float4 av = *(const float4*)(h + (size_t)rowA*128 + kt + kc);
        float4 bv = *(const float4*)(Bptr + kt + kc);
        As[kc+0][ar]=av.x; As[kc+1][ar]=av.y; As[kc+2][ar]=av.z; As[kc+3][ar]=av.w;
        Bs[kc+0][ar]=bv.x; Bs[kc+1][ar]=bv.y; Bs[kc+2][ar]=bv.z; Bs[kc+3][ar]=bv.w;
        __syncthreads();
#pragma unroll
        for (int k = 0; k < 16; k++) {
            float a[4], bb[4];
#pragma unroll
            for (int i = 0; i < 4; i++) a[i]  = As[k][ty*4+i];
#pragma unroll
            for (int j = 0; j < 4; j++) bb[j] = Bs[k][tx*4+j];
#pragma unroll
            for (int i = 0; i < 4; i++)
#pragma unroll
                for (int j = 0; j < 4; j++)
                    acc[i][j] += a[i]*bb[j];
        }
        __syncthreads();
    }

#pragma unroll
    for (int i = 0; i < 4; i++) {
        int r = bm*64 + ty*4 + i;
        int c = r >> 4, b = r & 15;
#pragma unroll
        for (int j = 0; j < 4; j++) {
            int ee = bn*64 + tx*4 + j;
            float bias = (ee < 128) ? b1[ee] : b2[ee-128];
            float v = acc[i][j] + bias;
            v = v > 0.f ? v : 0.f;
            __nv_bfloat16 hi = __float2bfloat16(v);
            __nv_bfloat16 lo = __float2bfloat16(v - __bfloat162float(hi));
            size_t idx = ((size_t)(b*C + c))*D + (ee & 127);
            if (ee < 128) { g_h1hi[idx] = hi; g_h1lo[idx] = lo; }
            else          { g_h2hi[idx] = hi; g_h2lo[idx] = lo; }
        }
    }
}

// ------------------------------------------------- row softmax (axis=2, mask on j)
// dst_sel 0 -> g_P2hi (hi only, src=B_t); dst_sel 1 -> g_Btt hi/lo (src=B_new)
__global__ void __launch_bounds__(256) softmax_row_kernel(
    const float* __restrict__ src, const int* __restrict__ mask, int dst_sel)
{
    int b = blockIdx.x >> 10;
    int i = blockIdx.x & 1023;
    const float* row = src + ((size_t)b*C + i)*C;
    int t = threadIdx.x;

    float v[4];
    float mx = -3.4e38f;
#pragma unroll
    for (int u = 0; u < 4; u++) {
        int j = u*256 + t;
        float x = (mask[b*C + j] != 0) ? row[j] : NEGV;
        v[u] = x;
        mx = fmaxf(mx, x);
    }
    __shared__ float red[8];
    float w = mx;
#pragma unroll
    for (int o = 16; o > 0; o >>= 1) w = fmaxf(w, __shfl_xor_sync(0xffffffffu, w, o));
    if ((t & 31) == 0) red[t >> 5] = w;
    __syncthreads();
    mx = red[0];
#pragma unroll
    for (int q = 1; q < 8; q++) mx = fmaxf(mx, red[q]);
    __syncthreads();

    float s = 0.f;
#pragma unroll
    for (int u = 0; u < 4; u++) { v[u] = expf(v[u] - mx); s += v[u]; }
#pragma unroll
    for (int o = 16; o > 0; o >>= 1) s += __shfl_xor_sync(0xffffffffu, s, o);
    if ((t & 31) == 0) red[t >> 5] = s;
    __syncthreads();
    float tot = 0.f;
#pragma unroll
    for (int q = 0; q < 8; q++) tot += red[q];
    float inv = 1.0f / tot;

    size_t base = ((size_t)b*C + i)*C;
    if (dst_sel) {
#pragma unroll
        for (int u = 0; u < 4; u++) {
            float pv = v[u] * inv;
            __nv_bfloat16 hi = __float2bfloat16(pv);
            g_Btthi[base + u*256 + t] = hi;
            g_Bttlo[base + u*256 + t] = __float2bfloat16(pv - __bfloat162float(hi));
        }
    } else {
#pragma unroll
        for (int u = 0; u < 4; u++)
            g_P2hi[base + u*256 + t] = __float2bfloat16(v[u] * inv);
    }
}

// ----------------- fused masked-exp + transpose + column-sum of B_t ---------
// E[k,j] = mask[k] ? exp(B_t[k,j]) : 0 ; writes E^T[b][j][k] bf16 + g_sum[b][j]
__global__ void __launch_bounds__(256) ecolT_kernel(
    const float* __restrict__ Bt, const int* __restrict__ mask)
{
    __shared__ float tile[32][33];
    __shared__ float csum[8][32];
    int b  = blockIdx.z;
    int k0 = blockIdx.y * 32;
    int j0 = blockIdx.x * 32;
    int tx = threadIdx.x & 31, ty = threadIdx.x >> 5;

    const float* src = Bt + (size_t)b*CC;
    float part = 0.f;
#pragma unroll
    for (int r = ty; r < 32; r += 8) {
        int k = k0 + r;
        float e = mask[b*C + k] ? expf(src[(size_t)k*C + j0 + tx]) : 0.f;
        tile[r][tx] = e;
        part += e;
    }
    csum[ty][tx] = part;
    __syncthreads();
    if (ty == 0) {
        float s = 0.f;
#pragma unroll
        for (int q = 0; q < 8; q++) s += csum[q][tx];
        atomicAdd(g_sum + b*C + j0 + tx, s);
    }
#pragma unroll
    for (int r = ty; r < 32; r += 8) {
        float x = tile[tx][r];                 // E[k0+tx][j0+r]
        g_EThi[(size_t)b*CC + (size_t)(j0 + r)*C + k0 + tx] = __float2bfloat16(x);
    }
}

// ------------------------------------ hT transpose: h(c,b,d) -> [b][d][c] hi/lo
__global__ void __launch_bounds__(256) ht_transpose_kernel(const float* __restrict__ h)
{
    __shared__ float tile[32][33];
    int b  = blockIdx.z;
    int c0 = blockIdx.x * 32;
    int d0 = blockIdx.y * 32;
    int tx = threadIdx.x & 31, ty = threadIdx.x >> 5;

#pragma unroll
    for (int r = ty; r < 32; r += 8)
        tile[r][tx] = h[(size_t)((c0 + r)*16 + b)*128 + d0 + tx];
    __syncthreads();
#pragma unroll
    for (int r = ty; r < 32; r += 8) {
        float x = tile[tx][r];
        __nv_bfloat16 hi = __float2bfloat16(x);
        __nv_bfloat16 lo = __float2bfloat16(x - __bfloat162float(hi));
        size_t o = (size_t)b*D*C + (size_t)(d0 + r)*C + c0 + tx;
        g_hThi[o] = hi;
        g_hTlo[o] = lo;
    }
}

// ------------------------------------ weight stack + split ------------------
__global__ void __launch_bounds__(256) wsplit_kernel(
    const float* __restrict__ Wr, const float* __restrict__ Wg)
{
    int idx = blockIdx.x*256 + threadIdx.x;
    int n = idx >> 9, k = idx & 511;
    float x = (n < 128) ? Wr[n*512 + k] : Wg[(n-128)*512 + k];
    __nv_bfloat16 hi = __float2bfloat16(x);
    g_Whi[idx] = hi;
    g_Wlo[idx] = __float2bfloat16(x - __bfloat162float(hi));
}

// ============================ B_new tensor-core GEMM =========================
// 22 uniform 2-tile chunks, 4-deep cp.async pipeline:
//   c in [0,16): acc += P2hi . EThi^T  (single mma; unnormalized B1)
//   at c==16:    acc *= gamma / colsum[j]
//   c in [16,22): B0 = h1.h2^T split-bf16 as 6 single chunks
//                 (hh k0, hh k1, hl k0, hl k1, lh k0, lh k1)
__global__ void __launch_bounds__(256) bnew_mma_kernel(
    const float* __restrict__ gamma_p, float* __restrict__ out)
{
    extern __shared__ __nv_bfloat16 sm[];
    int tid = threadIdx.x, wid = tid >> 5, lid = tid & 31;
    int b = blockIdx.z, it = blockIdx.y, jt = blockIdx.x;
    int wm = wid & 1, wn = wid >> 1;
    uint32_t sb = smem_u32(sm);

    float acc[4][4][4] = {};
    float gma = gamma_p[0];
    int lrow = lid >> 2, lcol2 = (lid & 3) << 1;

    auto issue = [&](int c) {
        const __nv_bfloat16 *A, *Bp;
        size_t rs;
        if (c < 16) {
            A  = g_P2hi + ((size_t)b*C + (size_t)it*128)*C + (size_t)c*64;
            Bp = g_EThi + ((size_t)b*C + (size_t)jt*128)*C + (size_t)c*64;
            rs = C;
        } else {
            int tm = (c - 16) >> 1, kh = (c - 16) & 1;
            const __nv_bfloat16* A1 = (tm < 2)  ? g_h1hi : g_h1lo;
            const __nv_bfloat16* B1 = (tm == 1) ? g_h2lo : g_h2hi;
            A  = A1 + ((size_t)b*C + (size_t)it*128)*D + kh*64;
            Bp = B1 + ((size_t)b*C + (size_t)jt*128)*D + kh*64;
            rs = D;
        }
        issue_single(sb + (uint32_t)(c & 3)*BUF2_B, tid, A, Bp, rs);
    };

    issue(0); CP_COMMIT();
    issue(1); CP_COMMIT();
    issue(2); CP_COMMIT();
    issue(3); CP_COMMIT();

    for (int c = 0; c < 22; c++) {
        int n = 21 - c; if (n > 3) n = 3;
        switch (n) {
            case 3: CP_WAITN(3); break;
            case 2: CP_WAITN(2); break;
            case 1: CP_WAITN(1); break;
            default: CP_WAITN(0); break;
        }
        __syncthreads();
        if (c == 16) {
            const float* sums = g_sum + b*C + jt*128 + wn*32 + lcol2;
#pragma unroll
            for (int jn = 0; jn < 4; jn++) {
                float s0 = gma / sums[jn*8];
                float s1 = gma / sums[jn*8 + 1];
#pragma unroll
                for (int im = 0; im < 4; im++) {
                    acc[im][jn][0] *= s0;
                    acc[im][jn][1] *= s1;
                    acc[im][jn][2] *= s0;
                    acc[im][jn][3] *= s1;
                }
            }
        }
        compute_chunk1(sm + (c & 3)*BUF2_E, acc, wm, wn, lid);
        __syncthreads();
        if (c + 4 < 22) { issue(c + 4); CP_COMMIT(); }
    }

    // epilogue: zero diagonal, store fp32
    int gi0 = it*128 + wm*64 + lrow;
    int gj0 = jt*128 + wn*32 + lcol2;
    float* obase = out + (size_t)b*CC;
#pragma unroll
    for (int im = 0; im < 4; im++) {
        int r = gi0 + im*16;
#pragma unroll
        for (int jn = 0; jn < 4; jn++) {
            int cj = gj0 + jn*8;
            float2 v0 = make_float2(acc[im][jn][0], acc[im][jn][1]);
            float2 v1 = make_float2(acc[im][jn][2], acc[im][jn][3]);
            if (r == cj)        v0.x = 0.f;
            else if (r == cj+1) v0.y = 0.f;
            if (r+8 == cj)      v1.x = 0.f;
            else if (r+8 == cj+1) v1.y = 0.f;
            *(float2*)(obase + (size_t)r*C + cj)     = v0;
            *(float2*)(obase + (size_t)(r+8)*C + cj) = v1;
        }
    }
}

// ============================ h_tmp GEMM + m construction ====================
__global__ void __launch_bounds__(256) htmp_mma_kernel(const float* __restrict__ h)
{
    extern __shared__ __nv_bfloat16 sm[];
    int tid = threadIdx.x, wid = tid >> 5, lid = tid & 31;
    int it = blockIdx.x, b = blockIdx.y;
    int wm = wid & 1, wn = wid >> 1;
    uint32_t sb = smem_u32(sm);

    float acc[4][4][4] = {};

    auto issue = [&](int c, int buf) {
        size_t offA = ((size_t)b*C + (size_t)it*128)*C + (size_t)c*64;
        size_t offB = (size_t)b*D*C + (size_t)c*64;
        issue_tiles(sb + buf*BUF4_B, tid,
                    g_Btthi + offA, g_Bttlo + offA,
                    g_hThi + offB, g_hTlo + offB, C, C);
    };

    issue(0, 0); CP_COMMIT();
    for (int c = 0; c < 16; c++) {
        if (c + 1 < 16) { issue(c + 1, (c + 1) & 1); CP_COMMIT(); CP_WAITN(1); }
        else CP_WAITN(0);
        __syncthreads();
        compute_chunk(sm + (c & 1)*4*TILE_E, acc, wm, wn, lid);
        __syncthreads();
    }

    int lrow = lid >> 2, lcol2 = (lid & 3) << 1;
    int ci0 = it*128 + wm*64 + lrow;
    int d0  = wn*32 + lcol2;
#pragma unroll
    for (int im = 0; im < 4; im++) {
#pragma unroll
        for (int half = 0; half < 2; half++) {
            int cg = ci0 + im*16 + half*8;
            int r  = cg*16 + b;
#pragma unroll
            for (int jn = 0; jn < 4; jn++) {
                int dj = d0 + jn*8;
                float2 ht = half ? make_float2(acc[im][jn][2], acc[im][jn][3])
                                 : make_float2(acc[im][jn][0], acc[im][jn][1]);
                float2 hv = *(const float2*)(h + (size_t)r*128 + dj);
                float2 seg[4];
                seg[0] = hv;
                seg[1] = ht;
                seg[2] = make_float2(hv.x*ht.x, hv.y*ht.y);
                seg[3] = make_float2(hv.x-ht.x, hv.y-ht.y);
#pragma unroll
                for (int s = 0; s < 4; s++) {
                    __nv_bfloat162 hi, lo;
                    split2(seg[s], hi, lo);
                    size_t o = (size_t)r*512 + s*128 + dj;
                    *(__nv_bfloat162*)(g_mhi + o) = hi;
                    *(__nv_bfloat162*)(g_mlo + o) = lo;
                }
            }
        }
    }
}

// ============================ gate GEMM: z = m . W^T =========================
__global__ void __launch_bounds__(256) gate_mma_kernel()
{
    extern __shared__ __nv_bfloat16 sm[];
    int tid = threadIdx.x, wid = tid >> 5, lid = tid & 31;
    int bm = blockIdx.x, half = blockIdx.y;
    int wm = wid & 1, wn = wid >> 1;
    uint32_t sb = smem_u32(sm);

    float acc[4][4][4] = {};

    auto issue = [&](int c, int buf) {
        size_t offA = ((size_t)bm*128)*512 + (size_t)c*64;
        size_t offB = ((size_t)half*128)*512 + (size_t)c*64;
        issue_tiles(sb + buf*BUF4_B, tid,
                    g_mhi + offA, g_mlo + offA,
                    g_Whi + offB, g_Wlo + offB, 512, 512);
    };

    issue(0, 0); CP_COMMIT();
    for (int c = 0; c < 8; c++) {
        if (c + 1 < 8) { issue(c + 1, (c + 1) & 1); CP_COMMIT(); CP_WAITN(1); }
        else CP_WAITN(0);
        __syncthreads();
        compute_chunk(sm + (c & 1)*4*TILE_E, acc, wm, wn, lid);
        __syncthreads();
    }

    int lrow = lid >> 2, lcol2 = (lid & 3) << 1;
    int r0 = bm*128 + wm*64 + lrow;
    int n0 = half*128 + wn*32 + lcol2;
#pragma unroll
    for (int im = 0; im < 4; im++) {
        int r = r0 + im*16;
#pragma unroll
        for (int jn = 0; jn < 4; jn++) {
            int n = n0 + jn*8;
            *(float2*)(g_z + (size_t)r*256 + n)     = make_float2(acc[im][jn][0], acc[im][jn][1]);
            *(float2*)(g_z + (size_t)(r+8)*256 + n) = make_float2(acc[im][jn][2], acc[im][jn][3]);
        }
    }
}

// ------------------------------------------------ combine: o = x*g + (1-g)*h
__global__ void __launch_bounds__(256) combine_kernel(
    const float* __restrict__ h, float* __restrict__ o)
{
    int idx = blockIdx.x*256 + threadIdx.x;
    int r = idx >> 7, d = idx & 127;
    float zr = g_z[(size_t)r*256 + d];
    float zg = g_z[(size_t)r*256 + 128 + d];
    float x  = fmaxf(zr, 0.f);
    float gg = 1.0f / (1.0f + expf(-zg));
    float hv = h[(size_t)r*128 + d];
    o[(size_t)r*128 + d] = x*gg + (1.0f - gg)*hv;
}

// ---------------------------------------------------------------------------
extern "C" void kernel_launch(void* const* d_in, const int* in_sizes, int n_in,
                              void* d_out, int out_size)
{
    const float* h   = (const float*)d_in[0];
    const int*   hm  = (const int*)  d_in[1];
    const float* Bt  = (const float*)d_in[2];
    const float* W1w = (const float*)d_in[3];
    const float* W1b = (const float*)d_in[4];
    const float* W2w = (const float*)d_in[5];
    const float* W2b = (const float*)d_in[6];
    const float* gam = (const float*)d_in[7];
    const float* Wrw = (const float*)d_in[8];
    const float* Wgw = (const float*)d_in[9];

    float* o_out    = (float*)d_out;                 // (c,b,d)
    float* bnew_out = (float*)d_out + (size_t)CB*D;  // (b,i,j)

    const int MMA_SMEM = 2*BUF4_B;   // 147456 bytes (== 4*BUF2_B)
    cudaFuncSetAttribute(bnew_mma_kernel, cudaFuncAttributeMaxDynamicSharedMemorySize, MMA_SMEM);
    cudaFuncSetAttribute(htmp_mma_kernel, cudaFuncAttributeMaxDynamicSharedMemorySize, MMA_SMEM);
    cudaFuncSetAttribute(gate_mma_kernel, cudaFuncAttributeMaxDynamicSharedMemorySize, MMA_SMEM);

    zero_sum_kernel<<<BATCH*C/256, 256>>>();
    fc_kernel<<<dim3(CB/64, 4), 256>>>(h, W1w, W1b, W2w, W2b);
    ht_transpose_kernel<<<dim3(C/32, D/32, BATCH), 256>>>(h);
    wsplit_kernel<<<512, 256>>>(Wrw, Wgw);
    softmax_row_kernel<<<BATCH*C, 256>>>(Bt, hm, /*->P2 hi*/0);
    ecolT_kernel<<<dim3(32, 32, BATCH), 256>>>(Bt, hm);
    bnew_mma_kernel<<<dim3(C/128, C/128, BATCH), 256, MMA_SMEM>>>(gam, bnew_out);
    softmax_row_kernel<<<BATCH*C, 256>>>(bnew_out, hm, /*->Btt hi/lo*/1);
    htmp_mma_kernel<<<dim3(C/128, BATCH), 256, MMA_SMEM>>>(h);
    gate_mma_kernel<<<dim3(CB/128, 2), 256, MMA_SMEM>>>();
    combine_kernel<<<CB*128/256, 256>>>(h, o_out);
}

// round 7
// speedup vs baseline: 3.8461x; 1.0049x over previous
#include <cuda_runtime.h>
#include <cuda_bf16.h>
#include <math.h>
#include <cstdint>

#define C 1024
#define BATCH 16
#define D 128
#define CB (C*BATCH)
#define CC (C*C)

#define LDK 72                     // padded SMEM row (bf16 elems)
#define TILE_E (128*LDK)           // elems per tile
#define TILE_B (TILE_E*2)          // bytes per tile (18432)
#define BUF2_B (2*TILE_B)          // 2-tile buffer bytes
#define BUF2_E (2*TILE_E)
#define BUF4_B (4*TILE_B)          // 4-tile buffer bytes

// ---------------- scratch (static device memory, no runtime allocation) ----
__device__ __nv_bfloat16 g_Fhi[BATCH*CC];    // exp(B_t)*mask[col]     [b][i][k]
__device__ __nv_bfloat16 g_GThi[BATCH*CC];   // (exp(B_t)^T)*mask[col] [b][j][k]
__device__ float g_sumF[BATCH*C];            // row sums of F
__device__ float g_sumG[BATCH*C];            // row sums of G^T (col sums of G)
__device__ float g_sum2[BATCH*C];            // row sums of masked exp(B_new)
__device__ __nv_bfloat16 g_E2hi[BATCH*CC];   // masked exp(B_new) [b][i][j]
__device__ __nv_bfloat16 g_E2lo[BATCH*CC];
__device__ __nv_bfloat16 g_h1hi[CB*D];       // [b][c][d]
__device__ __nv_bfloat16 g_h1lo[CB*D];
__device__ __nv_bfloat16 g_h2hi[CB*D];
__device__ __nv_bfloat16 g_h2lo[CB*D];
__device__ __nv_bfloat16 g_hThi[BATCH*D*C];  // [b][d][c]
__device__ __nv_bfloat16 g_hTlo[BATCH*D*C];
__device__ __nv_bfloat16 g_mhi[(size_t)CB*384]; // m' = [h, ht, h*ht]
__device__ __nv_bfloat16 g_mlo[(size_t)CB*384];
__device__ __nv_bfloat16 g_Whi[256*384];     // folded [U;V;C] x {r,g}
__device__ __nv_bfloat16 g_Wlo[256*384];
__device__ float g_z[(size_t)CB*256];        // gate pre-activations

// ----------------------------------------------------------------- helpers
__device__ __forceinline__ uint32_t smem_u32(const void* p) {
    uint32_t a;
    asm("{ .reg .u64 t; cvta.to.shared.u64 t, %1; cvt.u32.u64 %0, t; }" : "=r"(a) : "l"(p));
    return a;
}
__device__ __forceinline__ void mma16816(float* c, const uint32_t* a, const uint32_t* b) {
    asm volatile(
        "mma.sync.aligned.m16n8k16.row.col.f32.bf16.bf16.f32 "
        "{%0,%1,%2,%3}, {%4,%5,%6,%7}, {%8,%9}, {%0,%1,%2,%3};"
        : "+f"(c[0]), "+f"(c[1]), "+f"(c[2]), "+f"(c[3])
        : "r"(a[0]), "r"(a[1]), "r"(a[2]), "r"(a[3]), "r"(b[0]), "r"(b[1]));
}
__device__ __forceinline__ void cp16(uint32_t s, const void* g) {
    asm volatile("cp.async.ca.shared.global [%0], [%1], 16;" :: "r"(s), "l"(g));
}
#define CP_COMMIT() asm volatile("cp.async.commit_group;" ::: "memory")
#define CP_WAITN(n) asm volatile("cp.async.wait_group %0;" :: "n"(n) : "memory")

__device__ __forceinline__ void split2(float2 v, __nv_bfloat162& hi, __nv_bfloat162& lo) {
    hi.x = __float2bfloat16(v.x); lo.x = __float2bfloat16(v.x - __bfloat162float(hi.x));
    hi.y = __float2bfloat16(v.y); lo.y = __float2bfloat16(v.y - __bfloat162float(hi.y));
}

// load one 2-tile chunk (A, B), 128 rows x 64 bf16 each
__device__ __forceinline__ void issue_single(
    uint32_t sb, int tid,
    const __nv_bfloat16* A, const __nv_bfloat16* Bp, size_t rs)
{
#pragma unroll
    for (int q = 0; q < 4; q++) {
        int idx = q*256 + tid;
        int row = idx >> 3, seg = idx & 7;
        size_t g = (size_t)row*rs + seg*8;
        uint32_t so = row*(LDK*2) + seg*16;
        cp16(sb +          so, A  + g);
        cp16(sb + TILE_B + so, Bp + g);
    }
}

// load one 4-tile chunk (Ah, Al, Bh, Bl)
__device__ __forceinline__ void issue_tiles(
    uint32_t sb, int tid,
    const __nv_bfloat16* Ah, const __nv_bfloat16* Al,
    const __nv_bfloat16* Bh, const __nv_bfloat16* Bl,
    size_t rsA, size_t rsB)
{
#pragma unroll
    for (int q = 0; q < 4; q++) {
        int idx = q*256 + tid;
        int row = idx >> 3, seg = idx & 7;
        size_t gA = (size_t)row*rsA + seg*8;
        size_t gB = (size_t)row*rsB + seg*8;
        uint32_t so = row*(LDK*2) + seg*16;
        cp16(sb +            so, Ah + gA);
        cp16(sb +   TILE_B + so, Al + gA);
        cp16(sb + 2*TILE_B + so, Bh + gB);
        cp16(sb + 3*TILE_B + so, Bl + gB);
    }
}

// single-precision chunk: acc += A.B^T
__device__ __forceinline__ void compute_chunk1(
    const __nv_bfloat16* base, float acc[4][4][4], int wm, int wn, int lid)
{
    const __nv_bfloat16* sA = base;
    const __nv_bfloat16* sB = base + TILE_E;
    int lrow = lid >> 2;
    int lcol2 = (lid & 3) << 1;
#pragma unroll
    for (int ks = 0; ks < 4; ks++) {
        int k0 = ks*16 + lcol2;
        uint32_t a[4][4];
        int rbase = wm*64 + lrow;
#pragma unroll
        for (int im = 0; im < 4; im++) {
            int r = rbase + im*16;
            a[im][0] = *(const uint32_t*)(sA + r*LDK + k0);
            a[im][1] = *(const uint32_t*)(sA + (r+8)*LDK + k0);
            a[im][2] = *(const uint32_t*)(sA + r*LDK + k0 + 8);
            a[im][3] = *(const uint32_t*)(sA + (r+8)*LDK + k0 + 8);
        }
        uint32_t bb[4][2];
        int nbase = wn*32 + lrow;
#pragma unroll
        for (int jn = 0; jn < 4; jn++) {
            int n = nbase + jn*8;
            bb[jn][0] = *(const uint32_t*)(sB + n*LDK + k0);
            bb[jn][1] = *(const uint32_t*)(sB + n*LDK + k0 + 8);
        }
#pragma unroll
        for (int im = 0; im < 4; im++)
#pragma unroll
            for (int jn = 0; jn < 4; jn++)
                mma16816(acc[im][jn], a[im], bb[jn]);
    }
}

// split-bf16 (3-mma) chunk: acc += A.B^T (hi.hi + hi.lo + lo.hi)
__device__ __forceinline__ void compute_chunk(
    const __nv_bfloat16* base, float acc[4][4][4], int wm, int wn, int lid)
{
    const __nv_bfloat16* sAh = base;
    const __nv_bfloat16* sAl = base + TILE_E;
    const __nv_bfloat16* sBh = base + 2*TILE_E;
    const __nv_bfloat16* sBl = base + 3*TILE_E;
    int lrow = lid >> 2;
    int lcol2 = (lid & 3) << 1;
#pragma unroll
    for (int ks = 0; ks < 4; ks++) {
        int k0 = ks*16 + lcol2;
        uint32_t ah[4][4], al[4][4];
        int rbase = wm*64 + lrow;
#pragma unroll
        for (int im = 0; im < 4; im++) {
            int r = rbase + im*16;
            ah[im][0] = *(const uint32_t*)(sAh + r*LDK + k0);
            ah[im][1] = *(const uint32_t*)(sAh + (r+8)*LDK + k0);
            ah[im][2] = *(const uint32_t*)(sAh + r*LDK + k0 + 8);
            ah[im][3] = *(const uint32_t*)(sAh + (r+8)*LDK + k0 + 8);
            al[im][0] = *(const uint32_t*)(sAl + r*LDK + k0);
            al[im][1] = *(const uint32_t*)(sAl + (r+8)*LDK + k0);
            al[im][2] = *(const uint32_t*)(sAl + r*LDK + k0 + 8);
            al[im][3] = *(const uint32_t*)(sAl + (r+8)*LDK + k0 + 8);
        }
        uint32_t bh[4][2], bl[4][2];
        int nbase = wn*32 + lrow;
#pragma unroll
        for (int jn = 0; jn < 4; jn++) {
            int n = nbase + jn*8;
            bh[jn][0] = *(const uint32_t*)(sBh + n*LDK + k0);
            bh[jn][1] = *(const uint32_t*)(sBh + n*LDK + k0 + 8);
            bl[jn][0] = *(const uint32_t*)(sBl + n*LDK + k0);
            bl[jn][1] = *(const uint32_t*)(sBl + n*LDK + k0 + 8);
        }
#pragma unroll
        for (int im = 0; im < 4; im++)
#pragma unroll
            for (int jn = 0; jn < 4; jn++) {
                mma16816(acc[im][jn], ah[im], bh[jn]);
                mma16816(acc[im][jn], ah[im], bl[jn]);
                mma16816(acc[im][jn], al[im], bh[jn]);
            }
    }
}

// ---------------------------------------------------------------- zero sums
__global__ void __launch_bounds__(256) zero_sum_kernel()
{
    int i = blockIdx.x*256 + threadIdx.x;        // 0 .. 3*BATCH*C-1
    if (i < BATCH*C)            g_sumF[i] = 0.f;
    else if (i < 2*BATCH*C)     g_sumG[i - BATCH*C] = 0.f;
    else                        g_sum2[i - 2*BATCH*C] = 0.f;
}

// ---------------------------------------------------------------- FC kernel
__global__ void __launch_bounds__(256) fc_kernel(
    const float* __restrict__ h,
    const float* __restrict__ W1, const float* __restrict__ b1,
    const float* __restrict__ W2, const float* __restrict__ b2)
{
    __shared__ float As[16][64];
    __shared__ float Bs[16][64];
    int t  = threadIdx.x;
    int tx = t & 15, ty = t >> 4;
    int bm = blockIdx.x, bn = blockIdx.y;

    float acc[4][4] = {};
    int ar = t >> 2;
    int kc = (t & 3) << 2;
    int rowA = bm*64 + ar;
    int e    = bn*64 + ar;
    const float* Bptr = (e < 128) ? (W1 + e*128) : (W2 + (e-128)*128);

    for (int kt = 0; kt < 128; kt += 16) {
        float4 av = *(const float4*)(h + (size_t)rowA*128 + kt + kc);
        float4 bv = *(const float4*)(Bptr + kt + kc);
        As[kc+0][ar]=av.x; As[kc+1][ar]=av.y; As[kc+2][ar]=av.z; As[kc+3][ar]=av.w;
        Bs[kc+0][ar]=bv.x; Bs[kc+1][ar]=bv.y; Bs[kc+2][ar]=bv.z; Bs[kc+3][ar]=bv.w;
        __syncthreads();
#pragma unroll
        for (int k = 0; k < 16; k++) {
            float a[4], bb[4];
#pragma unroll
            for (int i = 0; i < 4; i++) a[i]  = As[k][ty*4+i];
#pragma unroll
            for (int j = 0; j < 4; j++) bb[j] = Bs[k][tx*4+j];
#pragma unroll
            for (int i = 0; i < 4; i++)
#pragma unroll
                for (int j = 0; j < 4; j++)
                    acc[i][j] += a[i]*bb[j];
        }
        __syncthreads();
    }

#pragma unroll
    for (int i = 0; i < 4; i++) {
        int r = bm*64 + ty*4 + i;
        int c = r >> 4, b = r & 15;
#pragma unroll
        for (int j = 0; j < 4; j++) {
            int ee = bn*64 + tx*4 + j;
            float bias = (ee < 128) ? b1[ee] : b2[ee-128];
            float v = acc[i][j] + bias;
            v = v > 0.f ? v : 0.f;
            __nv_bfloat16 hi = __float2bfloat16(v);
            __nv_bfloat16 lo = __float2bfloat16(v - __bfloat162float(hi));
            size_t idx = ((size_t)(b*C + c))*D + (ee & 127);
            if (ee < 128) { g_h1hi[idx] = hi; g_h1lo[idx] = lo; }
            else          { g_h2hi[idx] = hi; g_h2lo[idx] = lo; }
        }
    }
}

// ----------------- fused exp of B_t: F, G^T, row/col sums -------------------
// F[i,k]  = exp(B_t[i,k]) * m[k]   (row-major, [b][i][k])
// GT[j,k] = exp(B_t[k,j]) * m[k]   (transposed, [b][j][k])
__global__ void __launch_bounds__(256) esplit_kernel(
    const float* __restrict__ Bt, const int* __restrict__ mask)
{
    __shared__ float tile[32][33];
    int b  = blockIdx.z;
    int x0 = blockIdx.y * 32;   // first index of B_t
    int y0 = blockIdx.x * 32;   // second index of B_t
    int tx = threadIdx.x & 31, ty = threadIdx.x >> 5;

    int my  = mask[b*C + y0 + tx];   // mask of this thread's column
    int mxT = mask[b*C + x0 + tx];   // mask of this thread's x (for transposed pass)
    const float* src = Bt + (size_t)b*CC;

#pragma unroll
    for (int r = ty; r < 32; r += 8) {
        int x = x0 + r;
        float E = __expf(src[(size_t)x*C + y0 + tx]);
        tile[r][tx] = E;
        float f = my ? E : 0.f;
        g_Fhi[(size_t)b*CC + (size_t)x*C + y0 + tx] = __float2bfloat16(f);
        float s = f;
#pragma unroll
        for (int o = 16; o > 0; o >>= 1) s += __shfl_xor_sync(0xffffffffu, s, o);
        if (tx == 0) atomicAdd(g_sumF + b*C + x, s);
    }
    __syncthreads();
#pragma unroll
    for (int r2 = ty; r2 < 32; r2 += 8) {
        int y = y0 + r2;
        float gv = mxT ? tile[tx][r2] : 0.f;
        g_GThi[(size_t)b*CC + (size_t)y*C + x0 + tx] = __float2bfloat16(gv);
        float s = gv;
#pragma unroll
        for (int o = 16; o > 0; o >>= 1) s += __shfl_xor_sync(0xffffffffu, s, o);
        if (tx == 0) atomicAdd(g_sumG + b*C + y, s);
    }
}

// ------------------------------------ hT transpose: h(c,b,d) -> [b][d][c] hi/lo
__global__ void __launch_bounds__(256) ht_transpose_kernel(const float* __restrict__ h)
{
    __shared__ float tile[32][33];
    int b  = blockIdx.z;
    int c0 = blockIdx.x * 32;
    int d0 = blockIdx.y * 32;
    int tx = threadIdx.x & 31, ty = threadIdx.x >> 5;

#pragma unroll
    for (int r = ty; r < 32; r += 8)
        tile[r][tx] = h[(size_t)((c0 + r)*16 + b)*128 + d0 + tx];
    __syncthreads();
#pragma unroll
    for (int r = ty; r < 32; r += 8) {
        float x = tile[tx][r];
        __nv_bfloat16 hi = __float2bfloat16(x);
        __nv_bfloat16 lo = __float2bfloat16(x - __bfloat162float(hi));
        size_t o = (size_t)b*D*C + (size_t)(d0 + r)*C + c0 + tx;
        g_hThi[o] = hi;
        g_hTlo[o] = lo;
    }
}

// --------- folded weight stack: W' rows n (0:128 r, 128:256 g), cols k<384 ---
// k in [0,128):   U = W0 + W3 = W[k] + W[384+k]
// k in [128,256): V = W1 - W3 = W[k] - W[k+256]
// k in [256,384): Cc = W2     = W[k]
__global__ void __launch_bounds__(256) wsplit_kernel(
    const float* __restrict__ Wr, const float* __restrict__ Wg)
{
    int idx = blockIdx.x*256 + threadIdx.x;      // 0 .. 256*384-1
    int n = idx / 384, k = idx % 384;
    const float* W = (n < 128) ? (Wr + n*512) : (Wg + (n-128)*512);
    float x;
    if (k < 128)       x = W[k] + W[384 + k];
    else if (k < 256)  x = W[k] - W[k + 256];     // W1 - W3  (fixed)
    else               x = W[k];
    __nv_bfloat16 hi = __float2bfloat16(x);
    g_Whi[idx] = hi;
    g_Wlo[idx] = __float2bfloat16(x - __bfloat162float(hi));
}

// ============================ B_new GEMM + fused softmax epilogue ===========
// c in [0,16): acc += F . GT^T (single mma, unnormalized)
// at c==16:    acc *= gamma / (rowsumF_i * colsumG_j)
// c in [16,22): B0 = h1.h2^T split-bf16 (hh,hh,hl,hl,lh,lh over 2 K-halves)
// epilogue: diag zero, write B_new fp32, e = mask*exp(B_new) -> E2 hi/lo + rowsums
__global__ void __launch_bounds__(256) bnew_mma_kernel(
    const float* __restrict__ gamma_p, const int* __restrict__ mask,
    float* __restrict__ out)
{
    extern __shared__ __nv_bfloat16 sm[];
    __shared__ int   sMask[128];
    __shared__ float sRow[128];
    int tid = threadIdx.x, wid = tid >> 5, lid = tid & 31;
    int b = blockIdx.z, it = blockIdx.y, jt = blockIdx.x;
    int wm = wid & 1, wn = wid >> 1;
    uint32_t sb = smem_u32(sm);

    if (tid < 128) { sMask[tid] = mask[b*C + jt*128 + tid]; sRow[tid] = 0.f; }

    float acc[4][4][4] = {};
    float gma = gamma_p[0];
    int lrow = lid >> 2, lcol2 = (lid & 3) << 1;

    auto issue = [&](int c) {
        const __nv_bfloat16 *A, *Bp;
        size_t rs;
        if (c < 16) {
            A  = g_Fhi  + ((size_t)b*C + (size_t)it*128)*C + (size_t)c*64;
            Bp = g_GThi + ((size_t)b*C + (size_t)jt*128)*C + (size_t)c*64;
            rs = C;
        } else {
            int tm = (c - 16) >> 1, kh = (c - 16) & 1;
            const __nv_bfloat16* A1 = (tm < 2)  ? g_h1hi : g_h1lo;
            const __nv_bfloat16* B1 = (tm == 1) ? g_h2lo : g_h2hi;
            A  = A1 + ((size_t)b*C + (size_t)it*128)*D + kh*64;
            Bp = B1 + ((size_t)b*C + (size_t)jt*128)*D + kh*64;
            rs = D;
        }
        issue_single(sb + (uint32_t)(c & 3)*BUF2_B, tid, A, Bp, rs);
    };

    issue(0); CP_COMMIT();
    issue(1); CP_COMMIT();
    issue(2); CP_COMMIT();
    issue(3); CP_COMMIT();

    for (int c = 0; c < 22; c++) {
        int n = 21 - c; if (n > 3) n = 3;
        switch (n) {
            case 3: CP_WAITN(3); break;
            case 2: CP_WAITN(2); break;
            case 1: CP_WAITN(1); break;
            default: CP_WAITN(0); break;
        }
        __syncthreads();
        if (c == 16) {
            float invR[8], invCv[8];
#pragma unroll
            for (int im = 0; im < 4; im++) {
                int r = it*128 + wm*64 + lrow + im*16;
                invR[2*im]   = gma / g_sumF[b*C + r];
                invR[2*im+1] = gma / g_sumF[b*C + r + 8];
            }
#pragma unroll
            for (int jn = 0; jn < 4; jn++) {
                int cj = jt*128 + wn*32 + lcol2 + jn*8;
                invCv[2*jn]   = 1.0f / g_sumG[b*C + cj];
                invCv[2*jn+1] = 1.0f / g_sumG[b*C + cj + 1];
            }
#pragma unroll
            for (int im = 0; im < 4; im++)
#pragma unroll
                for (int jn = 0; jn < 4; jn++) {
                    acc[im][jn][0] *= invR[2*im]   * invCv[2*jn];
                    acc[im][jn][1] *= invR[2*im]   * invCv[2*jn+1];
                    acc[im][jn][2] *= invR[2*im+1] * invCv[2*jn];
                    acc[im][jn][3] *= invR[2*im+1] * invCv[2*jn+1];
                }
        }
        compute_chunk1(sm + (c & 3)*BUF2_E, acc, wm, wn, lid);
        __syncthreads();
        if (c + 4 < 22) { issue(c + 4); CP_COMMIT(); }
    }

    // ---- epilogue: diag zero, store fp32, fused masked exp + row sums ----
    int gi0 = it*128 + wm*64 + lrow;
    int gj0 = jt*128 + wn*32 + lcol2;
    float* obase = out + (size_t)b*CC;
#pragma unroll
    for (int im = 0; im < 4; im++) {
        int r = gi0 + im*16;
        float rp0 = 0.f, rp1 = 0.f;
#pragma unroll
        for (int jn = 0; jn < 4; jn++) {
            int cj = gj0 + jn*8;
            int lc = wn*32 + lcol2 + jn*8;
            float2 v0 = make_float2(acc[im][jn][0], acc[im][jn][1]);
            float2 v1 = make_float2(acc[im][jn][2], acc[im][jn][3]);
            if (r == cj)        v0.x = 0.f;
            else if (r == cj+1) v0.y = 0.f;
            if (r+8 == cj)      v1.x = 0.f;
            else if (r+8 == cj+1) v1.y = 0.f;
            *(float2*)(obase + (size_t)r*C + cj)     = v0;
            *(float2*)(obase + (size_t)(r+8)*C + cj) = v1;

            int m0 = sMask[lc], m1 = sMask[lc+1];
            float2 e0 = make_float2(m0 ? __expf(v0.x) : 0.f, m1 ? __expf(v0.y) : 0.f);
            float2 e1 = make_float2(m0 ? __expf(v1.x) : 0.f, m1 ? __expf(v1.y) : 0.f);
            rp0 += e0.x + e0.y;
            rp1 += e1.x + e1.y;
            __nv_bfloat162 h0, l0, h1, l1;
            split2(e0, h0, l0);
            split2(e1, h1, l1);
            size_t o0 = (size_t)b*CC + (size_t)r*C + cj;
            size_t o1 = (size_t)b*CC + (size_t)(r+8)*C + cj;
            *(__nv_bfloat162*)(g_E2hi + o0) = h0;
            *(__nv_bfloat162*)(g_E2lo + o0) = l0;
            *(__nv_bfloat162*)(g_E2hi + o1) = h1;
            *(__nv_bfloat162*)(g_E2lo + o1) = l1;
        }
        atomicAdd(&sRow[wm*64 + lrow + im*16],     rp0);
        atomicAdd(&sRow[wm*64 + lrow + im*16 + 8], rp1);
    }
    __syncthreads();
    if (tid < 128) atomicAdd(g_sum2 + b*C + it*128 + tid, sRow[tid]);
}

// ============================ h_tmp GEMM + m' construction ===================
// h_tmp[i,d] = (1/S_i) * sum_j E2[i,j]*h[j,d];  m' = [h, ht, h*ht]
__global__ void __launch_bounds__(256) htmp_mma_kernel(const float* __restrict__ h)
{
    extern __shared__ __nv_bfloat16 sm[];
    int tid = threadIdx.x, wid = tid >> 5, lid = tid & 31;
    int it = blockIdx.x, b = blockIdx.y;
    int wm = wid & 1, wn = wid >> 1;
    uint32_t sb = smem_u32(sm);

    float acc[4][4][4] = {};

    auto issue = [&](int c, int buf) {
        size_t offA = ((size_t)b*C + (size_t)it*128)*C + (size_t)c*64;
        size_t offB = (size_t)b*D*C + (size_t)c*64;
        issue_tiles(sb + buf*BUF4_B, tid,
                    g_E2hi + offA, g_E2lo + offA,
                    g_hThi + offB, g_hTlo + offB, C, C);
    };

    issue(0, 0); CP_COMMIT();
    for (int c = 0; c < 16; c++) {
        if (c + 1 < 16) { issue(c + 1, (c + 1) & 1); CP_COMMIT(); CP_WAITN(1); }
        else CP_WAITN(0);
        __syncthreads();
        compute_chunk(sm + (c & 1)*4*TILE_E, acc, wm, wn, lid);
        __syncthreads();
    }

    int lrow = lid >> 2, lcol2 = (lid & 3) << 1;
    int ci0 = it*128 + wm*64 + lrow;
    int d0  = wn*32 + lcol2;
#pragma unroll
    for (int im = 0; im < 4; im++) {
#pragma unroll
        for (int half = 0; half < 2; half++) {
            int cg = ci0 + im*16 + half*8;
            int r  = cg*16 + b;
            float inv = 1.0f / g_sum2[b*C + cg];
#pragma unroll
            for (int jn = 0; jn < 4; jn++) {
                int dj = d0 + jn*8;
                float2 ht = half ? make_float2(acc[im][jn][2], acc[im][jn][3])
                                 : make_float2(acc[im][jn][0], acc[im][jn][1]);
                ht.x *= inv; ht.y *= inv;
                float2 hv = *(const float2*)(h + (size_t)r*128 + dj);
                float2 seg[3];
                seg[0] = hv;
                seg[1] = ht;
                seg[2] = make_float2(hv.x*ht.x, hv.y*ht.y);
#pragma unroll
                for (int s = 0; s < 3; s++) {
                    __nv_bfloat162 hi, lo;
                    split2(seg[s], hi, lo);
                    size_t o = (size_t)r*384 + s*128 + dj;
                    *(__nv_bfloat162*)(g_mhi + o) = hi;
                    *(__nv_bfloat162*)(g_mlo + o) = lo;
                }
            }
        }
    }
}

// ============================ gate GEMM: z = m' . W'^T =======================
__global__ void __launch_bounds__(256) gate_mma_kernel()
{
    extern __shared__ __nv_bfloat16 sm[];
    int tid = threadIdx.x, wid = tid >> 5, lid = tid & 31;
    int bm = blockIdx.x, half = blockIdx.y;
    int wm = wid & 1, wn = wid >> 1;
    uint32_t sb = smem_u32(sm);

    float acc[4][4][4] = {};

    auto issue = [&](int c, int buf) {
        size_t offA = ((size_t)bm*128)*384 + (size_t)c*64;
        size_t offB = ((size_t)half*128)*384 + (size_t)c*64;
        issue_tiles(sb + buf*BUF4_B, tid,
                    g_mhi + offA, g_mlo + offA,
                    g_Whi + offB, g_Wlo + offB, 384, 384);
    };

    issue(0, 0); CP_COMMIT();
    for (int c = 0; c < 6; c++) {
        if (c + 1 < 6) { issue(c + 1, (c + 1) & 1); CP_COMMIT(); CP_WAITN(1); }
        else CP_WAITN(0);
        __syncthreads();
        compute_chunk(sm + (c & 1)*4*TILE_E, acc, wm, wn, lid);
        __syncthreads();
    }

    int lrow = lid >> 2, lcol2 = (lid & 3) << 1;
    int r0 = bm*128 + wm*64 + lrow;
    int n0 = half*128 + wn*32 + lcol2;
#pragma unroll
    for (int im = 0; im < 4; im++) {
        int r = r0 + im*16;
#pragma unroll
        for (int jn = 0; jn < 4; jn++) {
            int n = n0 + jn*8;
            *(float2*)(g_z + (size_t)r*256 + n)     = make_float2(acc[im][jn][0], acc[im][jn][1]);
            *(float2*)(g_z + (size_t)(r+8)*256 + n) = make_float2(acc[im][jn][2], acc[im][jn][3]);
        }
    }
}

// ------------------------------------------------ combine: o = x*g + (1-g)*h
__global__ void __launch_bounds__(256) combine_kernel(
    const float* __restrict__ h, float* __restrict__ o)
{
    int idx = blockIdx.x*256 + threadIdx.x;
    int r = idx >> 7, d = idx & 127;
    float zr = g_z[(size_t)r*256 + d];
    float zg = g_z[(size_t)r*256 + 128 + d];
    float x  = fmaxf(zr, 0.f);
    float gg = 1.0f / (1.0f + __expf(-zg));
    float hv = h[(size_t)r*128 + d];
    o[(size_t)r*128 + d] = x*gg + (1.0f - gg)*hv;
}

// ---------------------------------------------------------------------------
extern "C" void kernel_launch(void* const* d_in, const int* in_sizes, int n_in,
                              void* d_out, int out_size)
{
    const float* h   = (const float*)d_in[0];
    const int*   hm  = (const int*)  d_in[1];
    const float* Bt  = (const float*)d_in[2];
    const float* W1w = (const float*)d_in[3];
    const float* W1b = (const float*)d_in[4];
    const float* W2w = (const float*)d_in[5];
    const float* W2b = (const float*)d_in[6];
    const float* gam = (const float*)d_in[7];
    const float* Wrw = (const float*)d_in[8];
    const float* Wgw = (const float*)d_in[9];

    float* o_out    = (float*)d_out;                 // (c,b,d)
    float* bnew_out = (float*)d_out + (size_t)CB*D;  // (b,i,j)

    const int MMA_SMEM = 2*BUF4_B;   // 147456 bytes (== 4*BUF2_B)
    cudaFuncSetAttribute(bnew_mma_kernel, cudaFuncAttributeMaxDynamicSharedMemorySize, MMA_SMEM);
    cudaFuncSetAttribute(htmp_mma_kernel, cudaFuncAttributeMaxDynamicSharedMemorySize, MMA_SMEM);
    cudaFuncSetAttribute(gate_mma_kernel, cudaFuncAttributeMaxDynamicSharedMemorySize, MMA_SMEM);

    zero_sum_kernel<<<3*BATCH*C/256, 256>>>();
    fc_kernel<<<dim3(CB/64, 4), 256>>>(h, W1w, W1b, W2w, W2b);
    ht_transpose_kernel<<<dim3(C/32, D/32, BATCH), 256>>>(h);
    wsplit_kernel<<<256*384/256, 256>>>(Wrw, Wgw);
    esplit_kernel<<<dim3(32, 32, BATCH), 256>>>(Bt, hm);
    bnew_mma_kernel<<<dim3(C/128, C/128, BATCH), 256, MMA_SMEM>>>(gam, hm, bnew_out);
    htmp_mma_kernel<<<dim3(C/128, BATCH), 256, MMA_SMEM>>>(h);
    gate_mma_kernel<<<dim3(CB/128, 2), 256, MMA_SMEM>>>();
    combine_kernel<<<CB*128/256, 256>>>(h, o_out);
}

// round 8
// speedup vs baseline: 3.9537x; 1.0280x over previous
#include <cuda_runtime.h>
#include <cuda_bf16.h>
#include <cuda_fp8.h>
#include <math.h>
#include <cstdint>

#define C 1024
#define BATCH 16
#define D 128
#define CB (C*BATCH)
#define CC (C*C)

#define LDK 72                     // padded SMEM row (bf16 elems)
#define TILE_E (128*LDK)           // elems per bf16 tile
#define TILE_B (TILE_E*2)          // bytes per bf16 tile (18432)
#define BUF2_B (2*TILE_B)          // 2-tile buffer bytes (36864)
#define BUF2_E (2*TILE_E)
#define BUF4_B (4*TILE_B)          // 4-tile buffer bytes

#define LDK8 80                    // padded fp8 SMEM row (bytes) - conflict-free
#define TILE8_B (128*LDK8)         // 10240 bytes per fp8 tile

// ---------------- scratch (static device memory, no runtime allocation) ----
__device__ uint8_t g_F8[BATCH*CC];           // e4m3 exp(B_t)*mask[col]   [b][i][k]
__device__ uint8_t g_GT8[BATCH*CC];          // e4m3 exp(B_t)^T*mask[col] [b][j][k]
__device__ float g_sumF[BATCH*C];            // row sums of F (fp32 exact)
__device__ float g_sumG[BATCH*C];            // col sums of G (fp32 exact)
__device__ float g_sum2[BATCH*C];            // row sums of masked exp(B_new)
__device__ __nv_bfloat16 g_E2hi[BATCH*CC];   // masked exp(B_new) [b][i][j]
__device__ __nv_bfloat16 g_E2lo[BATCH*CC];
__device__ __nv_bfloat16 g_h1hi[CB*D];       // [b][c][d]
__device__ __nv_bfloat16 g_h1lo[CB*D];
__device__ __nv_bfloat16 g_h2hi[CB*D];
__device__ __nv_bfloat16 g_h2lo[CB*D];
__device__ __nv_bfloat16 g_hThi[BATCH*D*C];  // [b][d][c]
__device__ __nv_bfloat16 g_hTlo[BATCH*D*C];
__device__ __nv_bfloat16 g_mhi[(size_t)CB*384]; // m' = [h, ht, h*ht]
__device__ __nv_bfloat16 g_mlo[(size_t)CB*384];
__device__ __nv_bfloat16 g_Whi[256*384];     // folded [U;V;C] x {r,g}
__device__ __nv_bfloat16 g_Wlo[256*384];
__device__ float g_z[(size_t)CB*256];        // gate pre-activations

// ----------------------------------------------------------------- helpers
__device__ __forceinline__ uint32_t smem_u32(const void* p) {
    uint32_t a;
    asm("{ .reg .u64 t; cvta.to.shared.u64 t, %1; cvt.u32.u64 %0, t; }" : "=r"(a) : "l"(p));
    return a;
}
__device__ __forceinline__ void mma16816(float* c, const uint32_t* a, const uint32_t* b) {
    asm volatile(
        "mma.sync.aligned.m16n8k16.row.col.f32.bf16.bf16.f32 "
        "{%0,%1,%2,%3}, {%4,%5,%6,%7}, {%8,%9}, {%0,%1,%2,%3};"
        : "+f"(c[0]), "+f"(c[1]), "+f"(c[2]), "+f"(c[3])
        : "r"(a[0]), "r"(a[1]), "r"(a[2]), "r"(a[3]), "r"(b[0]), "r"(b[1]));
}
__device__ __forceinline__ void mma16832f8(float* c, const uint32_t* a, const uint32_t* b) {
    asm volatile(
        "mma.sync.aligned.m16n8k32.row.col.f32.e4m3.e4m3.f32 "
        "{%0,%1,%2,%3}, {%4,%5,%6,%7}, {%8,%9}, {%0,%1,%2,%3};"
        : "+f"(c[0]), "+f"(c[1]), "+f"(c[2]), "+f"(c[3])
        : "r"(a[0]), "r"(a[1]), "r"(a[2]), "r"(a[3]), "r"(b[0]), "r"(b[1]));
}
__device__ __forceinline__ void cp16(uint32_t s, const void* g) {
    asm volatile("cp.async.ca.shared.global [%0], [%1], 16;" :: "r"(s), "l"(g));
}
#define CP_COMMIT() asm volatile("cp.async.commit_group;" ::: "memory")
#define CP_WAITN(n) asm volatile("cp.async.wait_group %0;" :: "n"(n) : "memory")

__device__ __forceinline__ void split2(float2 v, __nv_bfloat162& hi, __nv_bfloat162& lo) {
    hi.x = __float2bfloat16(v.x); lo.x = __float2bfloat16(v.x - __bfloat162float(hi.x));
    hi.y = __float2bfloat16(v.y); lo.y = __float2bfloat16(v.y - __bfloat162float(hi.y));
}

// load one 2-tile bf16 chunk (A, B), 128 rows x 64 bf16 each
__device__ __forceinline__ void issue_single(
    uint32_t sb, int tid,
    const __nv_bfloat16* A, const __nv_bfloat16* Bp, size_t rs)
{
#pragma unroll
    for (int q = 0; q < 4; q++) {
        int idx = q*256 + tid;
        int row = idx >> 3, seg = idx & 7;
        size_t g = (size_t)row*rs + seg*8;
        uint32_t so = row*(LDK*2) + seg*16;
        cp16(sb +          so, A  + g);
        cp16(sb + TILE_B + so, Bp + g);
    }
}

// load one 2-tile fp8 chunk (A, B), 128 rows x 64 e4m3 bytes each
__device__ __forceinline__ void issue_single_fp8(
    uint32_t sb, int tid, const uint8_t* A, const uint8_t* Bp, size_t rs)
{
#pragma unroll
    for (int q = 0; q < 4; q++) {
        int idx = q*256 + tid;                 // 0..1023
        int tile = idx >> 9;                   // 0: A, 1: B
        int row  = (idx >> 2) & 127;
        int seg  = idx & 3;
        const uint8_t* src = tile ? Bp : A;
        cp16(sb + tile*TILE8_B + row*LDK8 + seg*16,
             src + (size_t)row*rs + seg*16);
    }
}

// load one 4-tile bf16 chunk (Ah, Al, Bh, Bl)
__device__ __forceinline__ void issue_tiles(
    uint32_t sb, int tid,
    const __nv_bfloat16* Ah, const __nv_bfloat16* Al,
    const __nv_bfloat16* Bh, const __nv_bfloat16* Bl,
    size_t rsA, size_t rsB)
{
#pragma unroll
    for (int q = 0; q < 4; q++) {
        int idx = q*256 + tid;
        int row = idx >> 3, seg = idx & 7;
        size_t gA = (size_t)row*rsA + seg*8;
        size_t gB = (size_t)row*rsB + seg*8;
        uint32_t so = row*(LDK*2) + seg*16;
        cp16(sb +            so, Ah + gA);
        cp16(sb +   TILE_B + so, Al + gA);
        cp16(sb + 2*TILE_B + so, Bh + gB);
        cp16(sb + 3*TILE_B + so, Bl + gB);
    }
}

// bf16 single-precision chunk: acc += A.B^T
__device__ __forceinline__ void compute_chunk1(
    const __nv_bfloat16* base, float acc[4][4][4], int wm, int wn, int lid)
{
    const __nv_bfloat16* sA = base;
    const __nv_bfloat16* sB = base + TILE_E;
    int lrow = lid >> 2;
    int lcol2 = (lid & 3) << 1;
#pragma unroll
    for (int ks = 0; ks < 4; ks++) {
        int k0 = ks*16 + lcol2;
        uint32_t a[4][4];
        int rbase = wm*64 + lrow;
#pragma unroll
        for (int im = 0; im < 4; im++) {
            int r = rbase + im*16;
            a[im][0] = *(const uint32_t*)(sA + r*LDK + k0);
            a[im][1] = *(const uint32_t*)(sA + (r+8)*LDK + k0);
            a[im][2] = *(const uint32_t*)(sA + r*LDK + k0 + 8);
            a[im][3] = *(const uint32_t*)(sA + (r+8)*LDK + k0 + 8);
        }
        uint32_t bb[4][2];
        int nbase = wn*32 + lrow;
#pragma unroll
        for (int jn = 0; jn < 4; jn++) {
            int n = nbase + jn*8;
            bb[jn][0] = *(const uint32_t*)(sB + n*LDK + k0);
            bb[jn][1] = *(const uint32_t*)(sB + n*LDK + k0 + 8);
        }
#pragma unroll
        for (int im = 0; im < 4; im++)
#pragma unroll
            for (int jn = 0; jn < 4; jn++)
                mma16816(acc[im][jn], a[im], bb[jn]);
    }
}

// fp8 chunk (K=64): acc += A.B^T via 2 x m16n8k32 ksteps
__device__ __forceinline__ void compute_chunk_fp8(
    const uint8_t* base, float acc[4][4][4], int wm, int wn, int lid)
{
    const uint8_t* sA = base;
    const uint8_t* sB = base + TILE8_B;
    int lrow = lid >> 2;
    int l4 = (lid & 3) << 2;
#pragma unroll
    for (int ks = 0; ks < 2; ks++) {
        int koff = ks*32 + l4;
        uint32_t a[4][4];
        int rbase = wm*64 + lrow;
#pragma unroll
        for (int im = 0; im < 4; im++) {
            int r = rbase + im*16;
            a[im][0] = *(const uint32_t*)(sA + r*LDK8 + koff);
            a[im][1] = *(const uint32_t*)(sA + (r+8)*LDK8 + koff);
            a[im][2] = *(const uint32_t*)(sA + r*LDK8 + koff + 16);
            a[im][3] = *(const uint32_t*)(sA + (r+8)*LDK8 + koff + 16);
        }
        uint32_t bb[4][2];
        int nbase = wn*32 + lrow;
#pragma unroll
        for (int jn = 0; jn < 4; jn++) {
            int n = nbase + jn*8;
            bb[jn][0] = *(const uint32_t*)(sB + n*LDK8 + koff);
            bb[jn][1] = *(const uint32_t*)(sB + n*LDK8 + koff + 16);
        }
#pragma unroll
        for (int im = 0; im < 4; im++)
#pragma unroll
            for (int jn = 0; jn < 4; jn++)
                mma16832f8(acc[im][jn], a[im], bb[jn]);
    }
}

// split-bf16 (3-mma) chunk: acc += A.B^T (hi.hi + hi.lo + lo.hi)
__device__ __forceinline__ void compute_chunk(
    const __nv_bfloat16* base, float acc[4][4][4], int wm, int wn, int lid)
{
    const __nv_bfloat16* sAh = base;
    const __nv_bfloat16* sAl = base + TILE_E;
    const __nv_bfloat16* sBh = base + 2*TILE_E;
    const __nv_bfloat16* sBl = base + 3*TILE_E;
    int lrow = lid >> 2;
    int lcol2 = (lid & 3) << 1;
#pragma unroll
    for (int ks = 0; ks < 4; ks++) {
        int k0 = ks*16 + lcol2;
        uint32_t ah[4][4], al[4][4];
        int rbase = wm*64 + lrow;
#pragma unroll
        for (int im = 0; im < 4; im++) {
            int r = rbase + im*16;
            ah[im][0] = *(const uint32_t*)(sAh + r*LDK + k0);
            ah[im][1] = *(const uint32_t*)(sAh + (r+8)*LDK + k0);
            ah[im][2] = *(const uint32_t*)(sAh + r*LDK + k0 + 8);
            ah[im][3] = *(const uint32_t*)(sAh + (r+8)*LDK + k0 + 8);
            al[im][0] = *(const uint32_t*)(sAl + r*LDK + k0);
            al[im][1] = *(const uint32_t*)(sAl + (r+8)*LDK + k0);
            al[im][2] = *(const uint32_t*)(sAl + r*LDK + k0 + 8);
            al[im][3] = *(const uint32_t*)(sAl + (r+8)*LDK + k0 + 8);
        }
        uint32_t bh[4][2], bl[4][2];
        int nbase = wn*32 + lrow;
#pragma unroll
        for (int jn = 0; jn < 4; jn++) {
            int n = nbase + jn*8;
            bh[jn][0] = *(const uint32_t*)(sBh + n*LDK + k0);
            bh[jn][1] = *(const uint32_t*)(sBh + n*LDK + k0 + 8);
            bl[jn][0] = *(const uint32_t*)(sBl + n*LDK + k0);
            bl[jn][1] = *(const uint32_t*)(sBl + n*LDK + k0 + 8);
        }
#pragma unroll
        for (int im = 0; im < 4; im++)
#pragma unroll
            for (int jn = 0; jn < 4; jn++) {
                mma16816(acc[im][jn], ah[im], bh[jn]);
                mma16816(acc[im][jn], ah[im], bl[jn]);
                mma16816(acc[im][jn], al[im], bh[jn]);
            }
    }
}

// ---------------------------------------------------------------- FC kernel
__global__ void __launch_bounds__(256) fc_kernel(
    const float* __restrict__ h,
    const float* __restrict__ W1, const float* __restrict__ b1,
    const float* __restrict__ W2, const float* __restrict__ b2)
{
    __shared__ float As[16][64];
    __shared__ float Bs[16][64];
    int t  = threadIdx.x;
    int tx = t & 15, ty = t >> 4;
    int bm = blockIdx.x, bn = blockIdx.y;

    float acc[4][4] = {};
    int ar = t >> 2;
    int kc = (t & 3) << 2;
    int rowA = bm*64 + ar;
    int e    = bn*64 + ar;
    const float* Bptr = (e < 128) ? (W1 + e*128) : (W2 + (e-128)*128);

    for (int kt = 0; kt < 128; kt += 16) {
        float4 av = *(const float4*)(h + (size_t)rowA*128 + kt + kc);
        float4 bv = *(const float4*)(Bptr + kt + kc);
        As[kc+0][ar]=av.x; As[kc+1][ar]=av.y; As[kc+2][ar]=av.z; As[kc+3][ar]=av.w;
        Bs[kc+0][ar]=bv.x; Bs[kc+1][ar]=bv.y; Bs[kc+2][ar]=bv.z; Bs[kc+3][ar]=bv.w;
        __syncthreads();
#pragma unroll
        for (int k = 0; k < 16; k++) {
            float a[4], bb[4];
#pragma unroll
            for (int i = 0; i < 4; i++) a[i]  = As[k][ty*4+i];
#pragma unroll
            for (int j = 0; j < 4; j++) bb[j] = Bs[k][tx*4+j];
#pragma unroll
            for (int i = 0; i < 4; i++)
#pragma unroll
                for (int j = 0; j < 4; j++)
                    acc[i][j] += a[i]*bb[j];
        }
        __syncthreads();
    }

#pragma unroll
    for (int i = 0; i < 4; i++) {
        int r = bm*64 + ty*4 + i;
        int c = r >> 4, b = r & 15;
#pragma unroll
        for (int j = 0; j < 4; j++) {
            int ee = bn*64 + tx*4 + j;
            float bias = (ee < 128) ? b1[ee] : b2[ee-128];
            float v = acc[i][j] + bias;
            v = v > 0.f ? v : 0.f;
            __nv_bfloat16 hi = __float2bfloat16(v);
            __nv_bfloat16 lo = __float2bfloat16(v - __bfloat162float(hi));
            size_t idx = ((size_t)(b*C + c))*D + (ee & 127);
            if (ee < 128) { g_h1hi[idx] = hi; g_h1lo[idx] = lo; }
            else          { g_h2hi[idx] = hi; g_h2lo[idx] = lo; }
        }
    }
}

// ----------------- fused exp of B_t: F(e4m3), G^T(e4m3), row/col sums -------
__global__ void __launch_bounds__(256) esplit_kernel(
    const float* __restrict__ Bt, const int* __restrict__ mask)
{
    __shared__ float tile[32][33];
    int b  = blockIdx.z;
    int x0 = blockIdx.y * 32;
    int y0 = blockIdx.x * 32;
    int tx = threadIdx.x & 31, ty = threadIdx.x >> 5;

    int my  = mask[b*C + y0 + tx];
    int mxT = mask[b*C + x0 + tx];
    const float* src = Bt + (size_t)b*CC;

#pragma unroll
    for (int r = ty; r < 32; r += 8) {
        int x = x0 + r;
        float E = __expf(src[(size_t)x*C + y0 + tx]);
        tile[r][tx] = E;
        float f = my ? E : 0.f;
        g_F8[(size_t)b*CC + (size_t)x*C + y0 + tx] =
            (uint8_t)__nv_cvt_float_to_fp8(f, __NV_SATFINITE, __NV_E4M3);
        float s = f;
#pragma unroll
        for (int o = 16; o > 0; o >>= 1) s += __shfl_xor_sync(0xffffffffu, s, o);
        if (tx == 0) atomicAdd(g_sumF + b*C + x, s);
    }
    __syncthreads();
#pragma unroll
    for (int r2 = ty; r2 < 32; r2 += 8) {
        int y = y0 + r2;
        float gv = mxT ? tile[tx][r2] : 0.f;
        g_GT8[(size_t)b*CC + (size_t)y*C + x0 + tx] =
            (uint8_t)__nv_cvt_float_to_fp8(gv, __NV_SATFINITE, __NV_E4M3);
        float s = gv;
#pragma unroll
        for (int o = 16; o > 0; o >>= 1) s += __shfl_xor_sync(0xffffffffu, s, o);
        if (tx == 0) atomicAdd(g_sumG + b*C + y, s);
    }
}

// ------------------------------------ hT transpose: h(c,b,d) -> [b][d][c] hi/lo
__global__ void __launch_bounds__(256) ht_transpose_kernel(const float* __restrict__ h)
{
    __shared__ float tile[32][33];
    int b  = blockIdx.z;
    int c0 = blockIdx.x * 32;
    int d0 = blockIdx.y * 32;
    int tx = threadIdx.x & 31, ty = threadIdx.x >> 5;

#pragma unroll
    for (int r = ty; r < 32; r += 8)
        tile[r][tx] = h[(size_t)((c0 + r)*16 + b)*128 + d0 + tx];
    __syncthreads();
#pragma unroll
    for (int r = ty; r < 32; r += 8) {
        float x = tile[tx][r];
        __nv_bfloat16 hi = __float2bfloat16(x);
        __nv_bfloat16 lo = __float2bfloat16(x - __bfloat162float(hi));
        size_t o = (size_t)b*D*C + (size_t)(d0 + r)*C + c0 + tx;
        g_hThi[o] = hi;
        g_hTlo[o] = lo;
    }
}

// --------- folded weight stack + sum zeroing (runs before esplit) ----------
__global__ void __launch_bounds__(256) wsplit_kernel(
    const float* __restrict__ Wr, const float* __restrict__ Wg)
{
    int idx = blockIdx.x*256 + threadIdx.x;      // 0 .. 256*384-1
    if (idx < 3*BATCH*C) {                       // zero the three sum arrays
        if (idx < BATCH*C)          g_sumF[idx] = 0.f;
        else if (idx < 2*BATCH*C)   g_sumG[idx - BATCH*C] = 0.f;
        else                        g_sum2[idx - 2*BATCH*C] = 0.f;
    }
    int n = idx / 384, k = idx % 384;
    const float* W = (n < 128) ? (Wr + n*512) : (Wg + (n-128)*512);
    float x;
    if (k < 128)       x = W[k] + W[384 + k];
    else if (k < 256)  x = W[k] - W[k + 256];     // W1 - W3
    else               x = W[k];
    __nv_bfloat16 hi = __float2bfloat16(x);
    g_Whi[idx] = hi;
    g_Wlo[idx] = __float2bfloat16(x - __bfloat162float(hi));
}

// ============================ B_new GEMM + fused softmax epilogue ===========
// c in [0,16): acc += F8 . GT8^T (fp8 mma, unnormalized)
// at c==16:    acc *= gamma / (rowsumF_i * colsumG_j)
// c in [16,22): B0 = h1.h2^T split-bf16 chunks
// epilogue: diag zero, write B_new fp32, e = mask*exp(B_new) -> E2 hi/lo + rowsums
__global__ void __launch_bounds__(256, 2) bnew_mma_kernel(
    const float* __restrict__ gamma_p, const int* __restrict__ mask,
    float* __restrict__ out)
{
    extern __shared__ char smc[];
    __shared__ int   sMask[128];
    __shared__ float sRow[128];
    int tid = threadIdx.x, wid = tid >> 5, lid = tid & 31;
    int b = blockIdx.z, it = blockIdx.y, jt = blockIdx.x;
    int wm = wid & 1, wn = wid >> 1;
    uint32_t sb = smem_u32(smc);

    if (tid < 128) { sMask[tid] = mask[b*C + jt*128 + tid]; sRow[tid] = 0.f; }

    float acc[4][4][4] = {};
    float gma = gamma_p[0];
    int lrow = lid >> 2, lcol2 = (lid & 3) << 1;

    auto issue = [&](int c) {
        uint32_t slot = sb + (uint32_t)(c % 3)*BUF2_B;
        if (c < 16) {
            const uint8_t* A  = g_F8  + ((size_t)b*C + (size_t)it*128)*C + (size_t)c*64;
            const uint8_t* Bp = g_GT8 + ((size_t)b*C + (size_t)jt*128)*C + (size_t)c*64;
            issue_single_fp8(slot, tid, A, Bp, C);
        } else {
            int tm = (c - 16) >> 1, kh = (c - 16) & 1;
            const __nv_bfloat16* A1 = (tm < 2)  ? g_h1hi : g_h1lo;
            const __nv_bfloat16* B1 = (tm == 1) ? g_h2lo : g_h2hi;
            issue_single(slot, tid,
                         A1 + ((size_t)b*C + (size_t)it*128)*D + kh*64,
                         B1 + ((size_t)b*C + (size_t)jt*128)*D + kh*64, D);
        }
    };

    issue(0); CP_COMMIT();
    issue(1); CP_COMMIT();
    issue(2); CP_COMMIT();

    for (int c = 0; c < 22; c++) {
        int n = 21 - c; if (n > 2) n = 2;
        switch (n) {
            case 2: CP_WAITN(2); break;
            case 1: CP_WAITN(1); break;
            default: CP_WAITN(0); break;
        }
        __syncthreads();
        if (c == 16) {
            float invR[8], invCv[8];
#pragma unroll
            for (int im = 0; im < 4; im++) {
                int r = it*128 + wm*64 + lrow + im*16;
                invR[2*im]   = gma / g_sumF[b*C + r];
                invR[2*im+1] = gma / g_sumF[b*C + r + 8];
            }
#pragma unroll
            for (int jn = 0; jn < 4; jn++) {
                int cj = jt*128 + wn*32 + lcol2 + jn*8;
                invCv[2*jn]   = 1.0f / g_sumG[b*C + cj];
                invCv[2*jn+1] = 1.0f / g_sumG[b*C + cj + 1];
            }
#pragma unroll
            for (int im = 0; im < 4; im++)
#pragma unroll
                for (int jn = 0; jn < 4; jn++) {
                    acc[im][jn][0] *= invR[2*im]   * invCv[2*jn];
                    acc[im][jn][1] *= invR[2*im]   * invCv[2*jn+1];
                    acc[im][jn][2] *= invR[2*im+1] * invCv[2*jn];
                    acc[im][jn][3] *= invR[2*im+1] * invCv[2*jn+1];
                }
        }
        char* base = smc + (c % 3)*BUF2_B;
        if (c < 16) compute_chunk_fp8((const uint8_t*)base, acc, wm, wn, lid);
        else        compute_chunk1((const __nv_bfloat16*)base, acc, wm, wn, lid);
        __syncthreads();
        if (c + 3 < 22) { issue(c + 3); CP_COMMIT(); }
    }

    // ---- epilogue: diag zero, store fp32, fused masked exp + row sums ----
    int gi0 = it*128 + wm*64 + lrow;
    int gj0 = jt*128 + wn*32 + lcol2;
    float* obase = out + (size_t)b*CC;
#pragma unroll
    for (int im = 0; im < 4; im++) {
        int r = gi0 + im*16;
        float rp0 = 0.f, rp1 = 0.f;
#pragma unroll
        for (int jn = 0; jn < 4; jn++) {
            int cj = gj0 + jn*8;
            int lc = wn*32 + lcol2 + jn*8;
            float2 v0 = make_float2(acc[im][jn][0], acc[im][jn][1]);
            float2 v1 = make_float2(acc[im][jn][2], acc[im][jn][3]);
            if (r == cj)        v0.x = 0.f;
            else if (r == cj+1) v0.y = 0.f;
            if (r+8 == cj)      v1.x = 0.f;
            else if (r+8 == cj+1) v1.y = 0.f;
            *(float2*)(obase + (size_t)r*C + cj)     = v0;
            *(float2*)(obase + (size_t)(r+8)*C + cj) = v1;

            int m0 = sMask[lc], m1 = sMask[lc+1];
            float2 e0 = make_float2(m0 ? __expf(v0.x) : 0.f, m1 ? __expf(v0.y) : 0.f);
            float2 e1 = make_float2(m0 ? __expf(v1.x) : 0.f, m1 ? __expf(v1.y) : 0.f);
            rp0 += e0.x + e0.y;
            rp1 += e1.x + e1.y;
            __nv_bfloat162 h0, l0, h1, l1;
            split2(e0, h0, l0);
            split2(e1, h1, l1);
            size_t o0 = (size_t)b*CC + (size_t)r*C + cj;
            size_t o1 = (size_t)b*CC + (size_t)(r+8)*C + cj;
            *(__nv_bfloat162*)(g_E2hi + o0) = h0;
            *(__nv_bfloat162*)(g_E2lo + o0) = l0;
            *(__nv_bfloat162*)(g_E2hi + o1) = h1;
            *(__nv_bfloat162*)(g_E2lo + o1) = l1;
        }
        atomicAdd(&sRow[wm*64 + lrow + im*16],     rp0);
        atomicAdd(&sRow[wm*64 + lrow + im*16 + 8], rp1);
    }
    __syncthreads();
    if (tid < 128) atomicAdd(g_sum2 + b*C + it*128 + tid, sRow[tid]);
}

// ============================ h_tmp GEMM + m' construction ===================
__global__ void __launch_bounds__(256) htmp_mma_kernel(const float* __restrict__ h)
{
    extern __shared__ char smc[];
    __nv_bfloat16* sm = (__nv_bfloat16*)smc;
    int tid = threadIdx.x, wid = tid >> 5, lid = tid & 31;
    int it = blockIdx.x, b = blockIdx.y;
    int wm = wid & 1, wn = wid >> 1;
    uint32_t sb = smem_u32(sm);

    float acc[4][4][4] = {};

    auto issue = [&](int c, int buf) {
        size_t offA = ((size_t)b*C + (size_t)it*128)*C + (size_t)c*64;
        size_t offB = (size_t)b*D*C + (size_t)c*64;
        issue_tiles(sb + buf*BUF4_B, tid,
                    g_E2hi + offA, g_E2lo + offA,
                    g_hThi + offB, g_hTlo + offB, C, C);
    };

    issue(0, 0); CP_COMMIT();
    for (int c = 0; c < 16; c++) {
        if (c + 1 < 16) { issue(c + 1, (c + 1) & 1); CP_COMMIT(); CP_WAITN(1); }
        else CP_WAITN(0);
        __syncthreads();
        compute_chunk(sm + (c & 1)*4*TILE_E, acc, wm, wn, lid);
        __syncthreads();
    }

    int lrow = lid >> 2, lcol2 = (lid & 3) << 1;
    int ci0 = it*128 + wm*64 + lrow;
    int d0  = wn*32 + lcol2;
#pragma unroll
    for (int im = 0; im < 4; im++) {
#pragma unroll
        for (int half = 0; half < 2; half++) {
            int cg = ci0 + im*16 + half*8;
            int r  = cg*16 + b;
            float inv = 1.0f / g_sum2[b*C + cg];
#pragma unroll
            for (int jn = 0; jn < 4; jn++) {
                int dj = d0 + jn*8;
                float2 ht = half ? make_float2(acc[im][jn][2], acc[im][jn][3])
                                 : make_float2(acc[im][jn][0], acc[im][jn][1]);
                ht.x *= inv; ht.y *= inv;
                float2 hv = *(const float2*)(h + (size_t)r*128 + dj);
                float2 seg[3];
                seg[0] = hv;
                seg[1] = ht;
                seg[2] = make_float2(hv.x*ht.x, hv.y*ht.y);
#pragma unroll
                for (int s = 0; s < 3; s++) {
                    __nv_bfloat162 hi, lo;
                    split2(seg[s], hi, lo);
                    size_t o = (size_t)r*384 + s*128 + dj;
                    *(__nv_bfloat162*)(g_mhi + o) = hi;
                    *(__nv_bfloat162*)(g_mlo + o) = lo;
                }
            }
        }
    }
}

// ============================ gate GEMM: z = m' . W'^T =======================
__global__ void __launch_bounds__(256) gate_mma_kernel()
{
    extern __shared__ char smc[];
    __nv_bfloat16* sm = (__nv_bfloat16*)smc;
    int tid = threadIdx.x, wid = tid >> 5, lid = tid & 31;
    int bm = blockIdx.x, half = blockIdx.y;
    int wm = wid & 1, wn = wid >> 1;
    uint32_t sb = smem_u32(sm);

    float acc[4][4][4] = {};

    auto issue = [&](int c, int buf) {
        size_t offA = ((size_t)bm*128)*384 + (size_t)c*64;
        size_t offB = ((size_t)half*128)*384 + (size_t)c*64;
        issue_tiles(sb + buf*BUF4_B, tid,
                    g_mhi + offA, g_mlo + offA,
                    g_Whi + offB, g_Wlo + offB, 384, 384);
    };

    issue(0, 0); CP_COMMIT();
    for (int c = 0; c < 6; c++) {
        if (c + 1 < 6) { issue(c + 1, (c + 1) & 1); CP_COMMIT(); CP_WAITN(1); }
        else CP_WAITN(0);
        __syncthreads();
        compute_chunk(sm + (c & 1)*4*TILE_E, acc, wm, wn, lid);
        __syncthreads();
    }

    int lrow = lid >> 2, lcol2 = (lid & 3) << 1;
    int r0 = bm*128 + wm*64 + lrow;
    int n0 = half*128 + wn*32 + lcol2;
#pragma unroll
    for (int im = 0; im < 4; im++) {
        int r = r0 + im*16;
#pragma unroll
        for (int jn = 0; jn < 4; jn++) {
            int n = n0 + jn*8;
            *(float2*)(g_z + (size_t)r*256 + n)     = make_float2(acc[im][jn][0], acc[im][jn][1]);
            *(float2*)(g_z + (size_t)(r+8)*256 + n) = make_float2(acc[im][jn][2], acc[im][jn][3]);
        }
    }
}

// ------------------------------------------------ combine: o = x*g + (1-g)*h
__global__ void __launch_bounds__(256) combine_kernel(
    const float* __restrict__ h, float* __restrict__ o)
{
    int idx = blockIdx.x*256 + threadIdx.x;
    int r = idx >> 7, d = idx & 127;
    float zr = g_z[(size_t)r*256 + d];
    float zg = g_z[(size_t)r*256 + 128 + d];
    float x  = fmaxf(zr, 0.f);
    float gg = 1.0f / (1.0f + __expf(-zg));
    float hv = h[(size_t)r*128 + d];
    o[(size_t)r*128 + d] = x*gg + (1.0f - gg)*hv;
}

// ---------------------------------------------------------------------------
extern "C" void kernel_launch(void* const* d_in, const int* in_sizes, int n_in,
                              void* d_out, int out_size)
{
    const float* h   = (const float*)d_in[0];
    const int*   hm  = (const int*)  d_in[1];
    const float* Bt  = (const float*)d_in[2];
    const float* W1w = (const float*)d_in[3];
    const float* W1b = (const float*)d_in[4];
    const float* W2w = (const float*)d_in[5];
    const float* W2b = (const float*)d_in[6];
    const float* gam = (const float*)d_in[7];
    const float* Wrw = (const float*)d_in[8];
    const float* Wgw = (const float*)d_in[9];

    float* o_out    = (float*)d_out;                 // (c,b,d)
    float* bnew_out = (float*)d_out + (size_t)CB*D;  // (b,i,j)

    const int BNEW_SMEM = 3*BUF2_B;   // 110592 bytes -> 2 CTAs/SM
    const int MMA_SMEM  = 2*BUF4_B;   // 147456 bytes
    cudaFuncSetAttribute(bnew_mma_kernel, cudaFuncAttributeMaxDynamicSharedMemorySize, BNEW_SMEM);
    cudaFuncSetAttribute(htmp_mma_kernel, cudaFuncAttributeMaxDynamicSharedMemorySize, MMA_SMEM);
    cudaFuncSetAttribute(gate_mma_kernel, cudaFuncAttributeMaxDynamicSharedMemorySize, MMA_SMEM);

    wsplit_kernel<<<256*384/256, 256>>>(Wrw, Wgw);   // also zeroes sums
    fc_kernel<<<dim3(CB/64, 4), 256>>>(h, W1w, W1b, W2w, W2b);
    ht_transpose_kernel<<<dim3(C/32, D/32, BATCH), 256>>>(h);
    esplit_kernel<<<dim3(32, 32, BATCH), 256>>>(Bt, hm);
    bnew_mma_kernel<<<dim3(C/128, C/128, BATCH), 256, BNEW_SMEM>>>(gam, hm, bnew_out);
    htmp_mma_kernel<<<dim3(C/128, BATCH), 256, MMA_SMEM>>>(h);
    gate_mma_kernel<<<dim3(CB/128, 2), 256, MMA_SMEM>>>();
    combine_kernel<<<CB*128/256, 256>>>(h, o_out);
}

// round 9
// speedup vs baseline: 4.2687x; 1.0797x over previous
#include <cuda_runtime.h>
#include <cuda_bf16.h>
#include <cuda_fp8.h>
#include <math.h>
#include <cstdint>

#define C 1024
#define BATCH 16
#define D 128
#define CB (C*BATCH)
#define CC (C*C)

#define LDK 72                     // padded SMEM row (bf16 elems)
#define TILE_E (128*LDK)           // elems per bf16 tile
#define TILE_B (TILE_E*2)          // bytes per bf16 tile (18432)
#define BUF2_B (2*TILE_B)          // 2-tile slot bytes (36864)
#define BUF4_B (4*TILE_B)          // 4-tile buffer bytes

#define LDK8 144                   // padded fp8 row (bytes), K=128: bank-perfect
#define TILE8_B (128*LDK8)         // 18432 bytes = TILE_B (reuses slot layout)

// ---------------- scratch (static device memory, no runtime allocation) ----
__device__ uint8_t g_F8[BATCH*CC];           // e4m3 exp(B_t)*mask[col]   [b][i][k]
__device__ uint8_t g_GT8[BATCH*CC];          // e4m3 exp(B_t)^T*mask[col] [b][j][k]
__device__ float g_sumF[BATCH*C];
__device__ float g_sumG[BATCH*C];
__device__ float g_sum2[BATCH*C];
__device__ __nv_bfloat16 g_E2hi[BATCH*CC];   // masked exp(B_new) [b][i][j]
__device__ __nv_bfloat16 g_E2lo[BATCH*CC];
__device__ __nv_bfloat16 g_h1hi[CB*D];
__device__ __nv_bfloat16 g_h1lo[CB*D];
__device__ __nv_bfloat16 g_h2hi[CB*D];
__device__ __nv_bfloat16 g_h2lo[CB*D];
__device__ __nv_bfloat16 g_hThi[BATCH*D*C];  // [b][d][c]
__device__ __nv_bfloat16 g_hTlo[BATCH*D*C];
__device__ __nv_bfloat16 g_mhi[(size_t)CB*384]; // m' = [h, ht, h*ht]
__device__ __nv_bfloat16 g_mlo[(size_t)CB*384];
__device__ __nv_bfloat16 g_Whi[256*384];
__device__ __nv_bfloat16 g_Wlo[256*384];
__device__ float g_z[(size_t)CB*256];

// ----------------------------------------------------------------- helpers
__device__ __forceinline__ uint32_t smem_u32(const void* p) {
    uint32_t a;
    asm("{ .reg .u64 t; cvta.to.shared.u64 t, %1; cvt.u32.u64 %0, t; }" : "=r"(a) : "l"(p));
    return a;
}
__device__ __forceinline__ void mma16816(float* c, const uint32_t* a, const uint32_t* b) {
    asm volatile(
        "mma.sync.aligned.m16n8k16.row.col.f32.bf16.bf16.f32 "
        "{%0,%1,%2,%3}, {%4,%5,%6,%7}, {%8,%9}, {%0,%1,%2,%3};"
        : "+f"(c[0]), "+f"(c[1]), "+f"(c[2]), "+f"(c[3])
        : "r"(a[0]), "r"(a[1]), "r"(a[2]), "r"(a[3]), "r"(b[0]), "r"(b[1]));
}
__device__ __forceinline__ void mma16832f8(float* c, const uint32_t* a, const uint32_t* b) {
    asm volatile(
        "mma.sync.aligned.m16n8k32.row.col.f32.e4m3.e4m3.f32 "
        "{%0,%1,%2,%3}, {%4,%5,%6,%7}, {%8,%9}, {%0,%1,%2,%3};"
        : "+f"(c[0]), "+f"(c[1]), "+f"(c[2]), "+f"(c[3])
        : "r"(a[0]), "r"(a[1]), "r"(a[2]), "r"(a[3]), "r"(b[0]), "r"(b[1]));
}
__device__ __forceinline__ void cp16(uint32_t s, const void* g) {
    asm volatile("cp.async.ca.shared.global [%0], [%1], 16;" :: "r"(s), "l"(g));
}
#define CP_COMMIT() asm volatile("cp.async.commit_group;" ::: "memory")
#define CP_WAITN(n) asm volatile("cp.async.wait_group %0;" :: "n"(n) : "memory")

__device__ __forceinline__ void split2(float2 v, __nv_bfloat162& hi, __nv_bfloat162& lo) {
    hi.x = __float2bfloat16(v.x); lo.x = __float2bfloat16(v.x - __bfloat162float(hi.x));
    hi.y = __float2bfloat16(v.y); lo.y = __float2bfloat16(v.y - __bfloat162float(hi.y));
}

// load one 2-tile bf16 chunk (A, B), 128 rows x 64 bf16 each
__device__ __forceinline__ void issue_single(
    uint32_t sb, int tid,
    const __nv_bfloat16* A, const __nv_bfloat16* Bp, size_t rs)
{
#pragma unroll
    for (int q = 0; q < 4; q++) {
        int idx = q*256 + tid;
        int row = idx >> 3, seg = idx & 7;
        size_t g = (size_t)row*rs + seg*8;
        uint32_t so = row*(LDK*2) + seg*16;
        cp16(sb +          so, A  + g);
        cp16(sb + TILE_B + so, Bp + g);
    }
}

// load one 2-tile fp8 chunk (A, B), 128 rows x 128 e4m3 bytes each (K=128)
__device__ __forceinline__ void issue_fp8_128(
    uint32_t sb, int tid, const uint8_t* A, const uint8_t* Bp, size_t rs)
{
#pragma unroll
    for (int q = 0; q < 8; q++) {
        int idx = q*256 + tid;                 // 0..2047
        int tile = idx >> 10;                  // 0: A, 1: B
        int row  = (idx >> 3) & 127;
        int seg  = idx & 7;
        const uint8_t* src = tile ? Bp : A;
        cp16(sb + tile*TILE8_B + row*LDK8 + seg*16,
             src + (size_t)row*rs + seg*16);
    }
}

// load one 4-tile bf16 chunk (Ah, Al, Bh, Bl)
__device__ __forceinline__ void issue_tiles(
    uint32_t sb, int tid,
    const __nv_bfloat16* Ah, const __nv_bfloat16* Al,
    const __nv_bfloat16* Bh, const __nv_bfloat16* Bl,
    size_t rsA, size_t rsB)
{
#pragma unroll
    for (int q = 0; q < 4; q++) {
        int idx = q*256 + tid;
        int row = idx >> 3, seg = idx & 7;
        size_t gA = (size_t)row*rsA + seg*8;
        size_t gB = (size_t)row*rsB + seg*8;
        uint32_t so = row*(LDK*2) + seg*16;
        cp16(sb +            so, Ah + gA);
        cp16(sb +   TILE_B + so, Al + gA);
        cp16(sb + 2*TILE_B + so, Bh + gB);
        cp16(sb + 3*TILE_B + so, Bl + gB);
    }
}

// bf16 single-precision chunk (K=64): acc += A.B^T
__device__ __forceinline__ void compute_chunk1(
    const __nv_bfloat16* base, float acc[4][4][4], int wm, int wn, int lid)
{
    const __nv_bfloat16* sA = base;
    const __nv_bfloat16* sB = base + TILE_E;
    int lrow = lid >> 2;
    int lcol2 = (lid & 3) << 1;
#pragma unroll
    for (int ks = 0; ks < 4; ks++) {
        int k0 = ks*16 + lcol2;
        uint32_t a[4][4];
        int rbase = wm*64 + lrow;
#pragma unroll
        for (int im = 0; im < 4; im++) {
            int r = rbase + im*16;
            a[im][0] = *(const uint32_t*)(sA + r*LDK + k0);
            a[im][1] = *(const uint32_t*)(sA + (r+8)*LDK + k0);
            a[im][2] = *(const uint32_t*)(sA + r*LDK + k0 + 8);
            a[im][3] = *(const uint32_t*)(sA + (r+8)*LDK + k0 + 8);
        }
        uint32_t bb[4][2];
        int nbase = wn*32 + lrow;
#pragma unroll
        for (int jn = 0; jn < 4; jn++) {
            int n = nbase + jn*8;
            bb[jn][0] = *(const uint32_t*)(sB + n*LDK + k0);
            bb[jn][1] = *(const uint32_t*)(sB + n*LDK + k0 + 8);
        }
#pragma unroll
        for (int im = 0; im < 4; im++)
#pragma unroll
            for (int jn = 0; jn < 4; jn++)
                mma16816(acc[im][jn], a[im], bb[jn]);
    }
}

// fp8 chunk (K=128): acc += A.B^T via 4 x m16n8k32 ksteps
__device__ __forceinline__ void compute_chunk_fp8(
    const uint8_t* base, float acc[4][4][4], int wm, int wn, int lid)
{
    const uint8_t* sA = base;
    const uint8_t* sB = base + TILE8_B;
    int lrow = lid >> 2;
    int l4 = (lid & 3) << 2;
#pragma unroll
    for (int ks = 0; ks < 4; ks++) {
        int koff = ks*32 + l4;
        uint32_t a[4][4];
        int rbase = wm*64 + lrow;
#pragma unroll
        for (int im = 0; im < 4; im++) {
            int r = rbase + im*16;
            a[im][0] = *(const uint32_t*)(sA + r*LDK8 + koff);
            a[im][1] = *(const uint32_t*)(sA + (r+8)*LDK8 + koff);
            a[im][2] = *(const uint32_t*)(sA + r*LDK8 + koff + 16);
            a[im][3] = *(const uint32_t*)(sA + (r+8)*LDK8 + koff + 16);
        }
        uint32_t bb[4][2];
        int nbase = wn*32 + lrow;
#pragma unroll
        for (int jn = 0; jn < 4; jn++) {
            int n = nbase + jn*8;
            bb[jn][0] = *(const uint32_t*)(sB + n*LDK8 + koff);
            bb[jn][1] = *(const uint32_t*)(sB + n*LDK8 + koff + 16);
        }
#pragma unroll
        for (int im = 0; im < 4; im++)
#pragma unroll
            for (int jn = 0; jn < 4; jn++)
                mma16832f8(acc[im][jn], a[im], bb[jn]);
    }
}

// split-bf16 (3-mma) chunk: acc += A.B^T (hi.hi + hi.lo + lo.hi)
__device__ __forceinline__ void compute_chunk(
    const __nv_bfloat16* base, float acc[4][4][4], int wm, int wn, int lid)
{
    const __nv_bfloat16* sAh = base;
    const __nv_bfloat16* sAl = base + TILE_E;
    const __nv_bfloat16* sBh = base + 2*TILE_E;
    const __nv_bfloat16* sBl = base + 3*TILE_E;
    int lrow = lid >> 2;
    int lcol2 = (lid & 3) << 1;
#pragma unroll
    for (int ks = 0; ks < 4; ks++) {
        int k0 = ks*16 + lcol2;
        uint32_t ah[4][4], al[4][4];
        int rbase = wm*64 + lrow;
#pragma unroll
        for (int im = 0; im < 4; im++) {
            int r = rbase + im*16;
            ah[im][0] = *(const uint32_t*)(sAh + r*LDK + k0);
            ah[im][1] = *(const uint32_t*)(sAh + (r+8)*LDK + k0);
            ah[im][2] = *(const uint32_t*)(sAh + r*LDK + k0 + 8);
            ah[im][3] = *(const uint32_t*)(sAh + (r+8)*LDK + k0 + 8);
            al[im][0] = *(const uint32_t*)(sAl + r*LDK + k0);
            al[im][1] = *(const uint32_t*)(sAl + (r+8)*LDK + k0);
            al[im][2] = *(const uint32_t*)(sAl + r*LDK + k0 + 8);
            al[im][3] = *(const uint32_t*)(sAl + (r+8)*LDK + k0 + 8);
        }
        uint32_t bh[4][2], bl[4][2];
        int nbase = wn*32 + lrow;
#pragma unroll
        for (int jn = 0; jn < 4; jn++) {
            int n = nbase + jn*8;
            bh[jn][0] = *(const uint32_t*)(sBh + n*LDK + k0);
            bh[jn][1] = *(const uint32_t*)(sBh + n*LDK + k0 + 8);
            bl[jn][0] = *(const uint32_t*)(sBl + n*LDK + k0);
            bl[jn][1] = *(const uint32_t*)(sBl + n*LDK + k0 + 8);
        }
#pragma unroll
        for (int im = 0; im < 4; im++)
#pragma unroll
            for (int jn = 0; jn < 4; jn++) {
                mma16816(acc[im][jn], ah[im], bh[jn]);
                mma16816(acc[im][jn], ah[im], bl[jn]);
                mma16816(acc[im][jn], al[im], bh[jn]);
            }
    }
}

// ---------------------------------------------------------------- FC kernel
__global__ void __launch_bounds__(256) fc_kernel(
    const float* __restrict__ h,
    const float* __restrict__ W1, const float* __restrict__ b1,
    const float* __restrict__ W2, const float* __restrict__ b2)
{
    __shared__ float As[16][64];
    __shared__ float Bs[16][64];
    int t  = threadIdx.x;
    int tx = t & 15, ty = t >> 4;
    int bm = blockIdx.x, bn = blockIdx.y;

    float acc[4][4] = {};
    int ar = t >> 2;
    int kc = (t & 3) << 2;
    int rowA = bm*64 + ar;
    int e    = bn*64 + ar;
    const float* Bptr = (e < 128) ? (W1 + e*128) : (W2 + (e-128)*128);

    for (int kt = 0; kt < 128; kt += 16) {
        float4 av = *(const float4*)(h + (size_t)rowA*128 + kt + kc);
        float4 bv = *(const float4*)(Bptr + kt + kc);
        As[kc+0][ar]=av.x; As[kc+1][ar]=av.y; As[kc+2][ar]=av.z; As[kc+3][ar]=av.w;
        Bs[kc+0][ar]=bv.x; Bs[kc+1][ar]=bv.y; Bs[kc+2][ar]=bv.z; Bs[kc+3][ar]=bv.w;
        __syncthreads();
#pragma unroll
        for (int k = 0; k < 16; k++) {
            float a[4], bb[4];
#pragma unroll
            for (int i = 0; i < 4; i++) a[i]  = As[k][ty*4+i];
#pragma unroll
            for (int j = 0; j < 4; j++) bb[j] = Bs[k][tx*4+j];
#pragma unroll
            for (int i = 0; i < 4; i++)
#pragma unroll
                for (int j = 0; j < 4; j++)
                    acc[i][j] += a[i]*bb[j];
        }
        __syncthreads();
    }

#pragma unroll
    for (int i = 0; i < 4; i++) {
        int r = bm*64 + ty*4 + i;
        int c = r >> 4, b = r & 15;
#pragma unroll
        for (int j = 0; j < 4; j++) {
            int ee = bn*64 + tx*4 + j;
            float bias = (ee < 128) ? b1[ee] : b2[ee-128];
            float v = acc[i][j] + bias;
            v = v > 0.f ? v : 0.f;
            __nv_bfloat16 hi = __float2bfloat16(v);
            __nv_bfloat16 lo = __float2bfloat16(v - __bfloat162float(hi));
            size_t idx = ((size_t)(b*C + c))*D + (ee & 127);
            if (ee < 128) { g_h1hi[idx] = hi; g_h1lo[idx] = lo; }
            else          { g_h2hi[idx] = hi; g_h2lo[idx] = lo; }
        }
    }
}

// ----------------- fused exp of B_t on 128x128 tiles ------------------------
// F[x][y] = exp(Bt[x][y])*m[y] -> g_F8 + row sums; GT[y][x] = exp(Bt[x][y])*m[x]
#define ETS 132   // padded tile stride (floats): 132*4=528 B (16-aligned, bank-free cols)
__global__ void __launch_bounds__(256) esplit_kernel(
    const float* __restrict__ Bt, const int* __restrict__ mask)
{
    extern __shared__ float tile[];   // [128][ETS]
    int b  = blockIdx.z;
    int x0 = blockIdx.y * 128;
    int y0 = blockIdx.x * 128;
    int w = threadIdx.x >> 5, lid = threadIdx.x & 31;

    int4 my4 = *(const int4*)(mask + b*C + y0 + lid*4);
    float mf0 = my4.x ? 1.f : 0.f, mf1 = my4.y ? 1.f : 0.f;
    float mf2 = my4.z ? 1.f : 0.f, mf3 = my4.w ? 1.f : 0.f;

    // pass 1: rows (F + row sums + raw tile)
#pragma unroll 4
    for (int i = 0; i < 16; i++) {
        int xl = w*16 + i;
        int x = x0 + xl;
        float4 v = *(const float4*)(Bt + (size_t)b*CC + (size_t)x*C + y0 + lid*4);
        float4 e;
        e.x = __expf(v.x); e.y = __expf(v.y); e.z = __expf(v.z); e.w = __expf(v.w);
        *(float4*)(tile + xl*ETS + lid*4) = e;
        float f0 = e.x*mf0, f1 = e.y*mf1, f2 = e.z*mf2, f3 = e.w*mf3;
        // pack 4 e4m3
        uint32_t pk =  (uint32_t)(uint8_t)__nv_cvt_float_to_fp8(f0, __NV_SATFINITE, __NV_E4M3)
                    | ((uint32_t)(uint8_t)__nv_cvt_float_to_fp8(f1, __NV_SATFINITE, __NV_E4M3) << 8)
                    | ((uint32_t)(uint8_t)__nv_cvt_float_to_fp8(f2, __NV_SATFINITE, __NV_E4M3) << 16)
                    | ((uint32_t)(uint8_t)__nv_cvt_float_to_fp8(f3, __NV_SATFINITE, __NV_E4M3) << 24);
        *(uint32_t*)(g_F8 + (size_t)b*CC + (size_t)x*C + y0 + lid*4) = pk;
        float s = f0 + f1 + f2 + f3;
#pragma unroll
        for (int o = 16; o > 0; o >>= 1) s += __shfl_xor_sync(0xffffffffu, s, o);
        if (lid == 0) atomicAdd(g_sumF + b*C + x, s);
    }
    __syncthreads();

    // pass 2: transposed rows (GT + col sums)
    float mx[4];
#pragma unroll
    for (int j = 0; j < 4; j++)
        mx[j] = mask[b*C + x0 + lid + j*32] ? 1.f : 0.f;
#pragma unroll 4
    for (int i = 0; i < 16; i++) {
        int yl = w*16 + i;
        int y = y0 + yl;
        float s = 0.f;
#pragma unroll
        for (int j = 0; j < 4; j++) {
            int xl = lid + j*32;
            float gv = tile[xl*ETS + yl] * mx[j];
            s += gv;
            g_GT8[(size_t)b*CC + (size_t)y*C + x0 + xl] =
                (uint8_t)__nv_cvt_float_to_fp8(gv, __NV_SATFINITE, __NV_E4M3);
        }
#pragma unroll
        for (int o = 16; o > 0; o >>= 1) s += __shfl_xor_sync(0xffffffffu, s, o);
        if (lid == 0) atomicAdd(g_sumG + b*C + y, s);
    }
}

// ------------------------------------ hT transpose: h(c,b,d) -> [b][d][c] hi/lo
__global__ void __launch_bounds__(256) ht_transpose_kernel(const float* __restrict__ h)
{
    __shared__ float tileT[32][33];
    int b  = blockIdx.z;
    int c0 = blockIdx.x * 32;
    int d0 = blockIdx.y * 32;
    int tx = threadIdx.x & 31, ty = threadIdx.x >> 5;

#pragma unroll
    for (int r = ty; r < 32; r += 8)
        tileT[r][tx] = h[(size_t)((c0 + r)*16 + b)*128 + d0 + tx];
    __syncthreads();
#pragma unroll
    for (int r = ty; r < 32; r += 8) {
        float x = tileT[tx][r];
        __nv_bfloat16 hi = __float2bfloat16(x);
        __nv_bfloat16 lo = __float2bfloat16(x - __bfloat162float(hi));
        size_t o = (size_t)b*D*C + (size_t)(d0 + r)*C + c0 + tx;
        g_hThi[o] = hi;
        g_hTlo[o] = lo;
    }
}

// --------- folded weight stack + sum zeroing --------------------------------
__global__ void __launch_bounds__(256) wsplit_kernel(
    const float* __restrict__ Wr, const float* __restrict__ Wg)
{
    int idx = blockIdx.x*256 + threadIdx.x;      // 0 .. 256*384-1
    if (idx < 3*BATCH*C) {
        if (idx < BATCH*C)          g_sumF[idx] = 0.f;
        else if (idx < 2*BATCH*C)   g_sumG[idx - BATCH*C] = 0.f;
        else                        g_sum2[idx - 2*BATCH*C] = 0.f;
    }
    int n = idx / 384, k = idx % 384;
    const float* W = (n < 128) ? (Wr + n*512) : (Wg + (n-128)*512);
    float x;
    if (k < 128)       x = W[k] + W[384 + k];
    else if (k < 256)  x = W[k] - W[k + 256];     // W1 - W3
    else               x = W[k];
    __nv_bfloat16 hi = __float2bfloat16(x);
    g_Whi[idx] = hi;
    g_Wlo[idx] = __float2bfloat16(x - __bfloat162float(hi));
}

// ============================ B_new GEMM + fused softmax epilogue ===========
// c in [0,8):  acc += F8 . GT8^T (fp8, K=128/chunk, unnormalized)
// at c==8:     acc *= gamma / (rowsumF_i * colsumG_j)
// c in [8,14): B0 = h1.h2^T split-bf16 (K=64 chunks: hh,hh,hl,hl,lh,lh)
__global__ void __launch_bounds__(256, 2) bnew_mma_kernel(
    const float* __restrict__ gamma_p, const int* __restrict__ mask,
    float* __restrict__ out)
{
    extern __shared__ char smc[];
    __shared__ int   sMask[128];
    __shared__ float sRow[128];
    int tid = threadIdx.x, wid = tid >> 5, lid = tid & 31;
    int b = blockIdx.z, it = blockIdx.y, jt = blockIdx.x;
    int wm = wid & 1, wn = wid >> 1;
    uint32_t sb = smem_u32(smc);

    if (tid < 128) { sMask[tid] = mask[b*C + jt*128 + tid]; sRow[tid] = 0.f; }

    float acc[4][4][4] = {};
    float gma = gamma_p[0];
    int lrow = lid >> 2, lcol2 = (lid & 3) << 1;

    auto issue = [&](int c) {
        uint32_t slot = sb + (uint32_t)(c % 3)*BUF2_B;
        if (c < 8) {
            const uint8_t* A  = g_F8  + ((size_t)b*C + (size_t)it*128)*C + (size_t)c*128;
            const uint8_t* Bp = g_GT8 + ((size_t)b*C + (size_t)jt*128)*C + (size_t)c*128;
            issue_fp8_128(slot, tid, A, Bp, C);
        } else {
            int tm = (c - 8) >> 1, kh = (c - 8) & 1;
            const __nv_bfloat16* A1 = (tm < 2)  ? g_h1hi : g_h1lo;
            const __nv_bfloat16* B1 = (tm == 1) ? g_h2lo : g_h2hi;
            issue_single(slot, tid,
                         A1 + ((size_t)b*C + (size_t)it*128)*D + kh*64,
                         B1 + ((size_t)b*C + (size_t)jt*128)*D + kh*64, D);
        }
    };

    issue(0); CP_COMMIT();
    issue(1); CP_COMMIT();
    issue(2); CP_COMMIT();

    for (int c = 0; c < 14; c++) {
        int n = 13 - c; if (n > 2) n = 2;
        switch (n) {
            case 2: CP_WAITN(2); break;
            case 1: CP_WAITN(1); break;
            default: CP_WAITN(0); break;
        }
        __syncthreads();
        if (c == 8) {
            float invR[8], invCv[8];
#pragma unroll
            for (int im = 0; im < 4; im++) {
                int r = it*128 + wm*64 + lrow + im*16;
                invR[2*im]   = gma / g_sumF[b*C + r];
                invR[2*im+1] = gma / g_sumF[b*C + r + 8];
            }
#pragma unroll
            for (int jn = 0; jn < 4; jn++) {
                int cj = jt*128 + wn*32 + lcol2 + jn*8;
                invCv[2*jn]   = 1.0f / g_sumG[b*C + cj];
                invCv[2*jn+1] = 1.0f / g_sumG[b*C + cj + 1];
            }
#pragma unroll
            for (int im = 0; im < 4; im++)
#pragma unroll
                for (int jn = 0; jn < 4; jn++) {
                    acc[im][jn][0] *= invR[2*im]   * invCv[2*jn];
                    acc[im][jn][1] *= invR[2*im]   * invCv[2*jn+1];
                    acc[im][jn][2] *= invR[2*im+1] * invCv[2*jn];
                    acc[im][jn][3] *= invR[2*im+1] * invCv[2*jn+1];
                }
        }
        char* base = smc + (c % 3)*BUF2_B;
        if (c < 8) compute_chunk_fp8((const uint8_t*)base, acc, wm, wn, lid);
        else       compute_chunk1((const __nv_bfloat16*)base, acc, wm, wn, lid);
        __syncthreads();
        if (c + 3 < 14) { issue(c + 3); CP_COMMIT(); }
    }

    // ---- epilogue: diag zero, store fp32, fused masked exp + row sums ----
    int gi0 = it*128 + wm*64 + lrow;
    int gj0 = jt*128 + wn*32 + lcol2;
    float* obase = out + (size_t)b*CC;
#pragma unroll
    for (int im = 0; im < 4; im++) {
        int r = gi0 + im*16;
        float rp0 = 0.f, rp1 = 0.f;
#pragma unroll
        for (int jn = 0; jn < 4; jn++) {
            int cj = gj0 + jn*8;
            int lc = wn*32 + lcol2 + jn*8;
            float2 v0 = make_float2(acc[im][jn][0], acc[im][jn][1]);
            float2 v1 = make_float2(acc[im][jn][2], acc[im][jn][3]);
            if (r == cj)        v0.x = 0.f;
            else if (r == cj+1) v0.y = 0.f;
            if (r+8 == cj)      v1.x = 0.f;
            else if (r+8 == cj+1) v1.y = 0.f;
            *(float2*)(obase + (size_t)r*C + cj)     = v0;
            *(float2*)(obase + (size_t)(r+8)*C + cj) = v1;

            int m0 = sMask[lc], m1 = sMask[lc+1];
            float2 e0 = make_float2(m0 ? __expf(v0.x) : 0.f, m1 ? __expf(v0.y) : 0.f);
            float2 e1 = make_float2(m0 ? __expf(v1.x) : 0.f, m1 ? __expf(v1.y) : 0.f);
            rp0 += e0.x + e0.y;
            rp1 += e1.x + e1.y;
            __nv_bfloat162 h0, l0, h1, l1;
            split2(e0, h0, l0);
            split2(e1, h1, l1);
            size_t o0 = (size_t)b*CC + (size_t)r*C + cj;
            size_t o1 = (size_t)b*CC + (size_t)(r+8)*C + cj;
            *(__nv_bfloat162*)(g_E2hi + o0) = h0;
            *(__nv_bfloat162*)(g_E2lo + o0) = l0;
            *(__nv_bfloat162*)(g_E2hi + o1) = h1;
            *(__nv_bfloat162*)(g_E2lo + o1) = l1;
        }
        atomicAdd(&sRow[wm*64 + lrow + im*16],     rp0);
        atomicAdd(&sRow[wm*64 + lrow + im*16 + 8], rp1);
    }
    __syncthreads();
    if (tid < 128) atomicAdd(g_sum2 + b*C + it*128 + tid, sRow[tid]);
}

// ============================ h_tmp GEMM + m' construction ===================
__global__ void __launch_bounds__(256) htmp_mma_kernel(const float* __restrict__ h)
{
    extern __shared__ char smc[];
    __nv_bfloat16* sm = (__nv_bfloat16*)smc;
    int tid = threadIdx.x, wid = tid >> 5, lid = tid & 31;
    int it = blockIdx.x, b = blockIdx.y;
    int wm = wid & 1, wn = wid >> 1;
    uint32_t sb = smem_u32(sm);

    float acc[4][4][4] = {};

    auto issue = [&](int c, int buf) {
        size_t offA = ((size_t)b*C + (size_t)it*128)*C + (size_t)c*64;
        size_t offB = (size_t)b*D*C + (size_t)c*64;
        issue_tiles(sb + buf*BUF4_B, tid,
                    g_E2hi + offA, g_E2lo + offA,
                    g_hThi + offB, g_hTlo + offB, C, C);
    };

    issue(0, 0); CP_COMMIT();
    for (int c = 0; c < 16; c++) {
        if (c + 1 < 16) { issue(c + 1, (c + 1) & 1); CP_COMMIT(); CP_WAITN(1); }
        else CP_WAITN(0);
        __syncthreads();
        compute_chunk(sm + (c & 1)*4*TILE_E, acc, wm, wn, lid);
        __syncthreads();
    }

    int lrow = lid >> 2, lcol2 = (lid & 3) << 1;
    int ci0 = it*128 + wm*64 + lrow;
    int d0  = wn*32 + lcol2;
#pragma unroll
    for (int im = 0; im < 4; im++) {
#pragma unroll
        for (int half = 0; half < 2; half++) {
            int cg = ci0 + im*16 + half*8;
            int r  = cg*16 + b;
            float inv = 1.0f / g_sum2[b*C + cg];
#pragma unroll
            for (int jn = 0; jn < 4; jn++) {
                int dj = d0 + jn*8;
                float2 ht = half ? make_float2(acc[im][jn][2], acc[im][jn][3])
                                 : make_float2(acc[im][jn][0], acc[im][jn][1]);
                ht.x *= inv; ht.y *= inv;
                float2 hv = *(const float2*)(h + (size_t)r*128 + dj);
                float2 seg[3];
                seg[0] = hv;
                seg[1] = ht;
                seg[2] = make_float2(hv.x*ht.x, hv.y*ht.y);
#pragma unroll
                for (int s = 0; s < 3; s++) {
                    __nv_bfloat162 hi, lo;
                    split2(seg[s], hi, lo);
                    size_t o = (size_t)r*384 + s*128 + dj;
                    *(__nv_bfloat162*)(g_mhi + o) = hi;
                    *(__nv_bfloat162*)(g_mlo + o) = lo;
                }
            }
        }
    }
}

// ============================ gate GEMM: z = m' . W'^T =======================
__global__ void __launch_bounds__(256) gate_mma_kernel()
{
    extern __shared__ char smc[];
    __nv_bfloat16* sm = (__nv_bfloat16*)smc;
    int tid = threadIdx.x, wid = tid >> 5, lid = tid & 31;
    int bm = blockIdx.x, half = blockIdx.y;
    int wm = wid & 1, wn = wid >> 1;
    uint32_t sb = smem_u32(sm);

    float acc[4][4][4] = {};

    auto issue = [&](int c, int buf) {
        size_t offA = ((size_t)bm*128)*384 + (size_t)c*64;
        size_t offB = ((size_t)half*128)*384 + (size_t)c*64;
        issue_tiles(sb + buf*BUF4_B, tid,
                    g_mhi + offA, g_mlo + offA,
                    g_Whi + offB, g_Wlo + offB, 384, 384);
    };

    issue(0, 0); CP_COMMIT();
    for (int c = 0; c < 6; c++) {
        if (c + 1 < 6) { issue(c + 1, (c + 1) & 1); CP_COMMIT(); CP_WAITN(1); }
        else CP_WAITN(0);
        __syncthreads();
        compute_chunk(sm + (c & 1)*4*TILE_E, acc, wm, wn, lid);
        __syncthreads();
    }

    int lrow = lid >> 2, lcol2 = (lid & 3) << 1;
    int r0 = bm*128 + wm*64 + lrow;
    int n0 = half*128 + wn*32 + lcol2;
#pragma unroll
    for (int im = 0; im < 4; im++) {
        int r = r0 + im*16;
#pragma unroll
        for (int jn = 0; jn < 4; jn++) {
            int n = n0 + jn*8;
            *(float2*)(g_z + (size_t)r*256 + n)     = make_float2(acc[im][jn][0], acc[im][jn][1]);
            *(float2*)(g_z + (size_t)(r+8)*256 + n) = make_float2(acc[im][jn][2], acc[im][jn][3]);
        }
    }
}

// ------------------------------------------------ combine: o = x*g + (1-g)*h
__global__ void __launch_bounds__(256) combine_kernel(
    const float* __restrict__ h, float* __restrict__ o)
{
    int idx = blockIdx.x*256 + threadIdx.x;   // over CB*32 float4 groups
    int r = idx >> 5, q = idx & 31;
    float4 zr = *(const float4*)(g_z + (size_t)r*256 + q*4);
    float4 zg = *(const float4*)(g_z + (size_t)r*256 + 128 + q*4);
    float4 hv = *(const float4*)(h + (size_t)r*128 + q*4);
    float4 ov;
    {
        float x = fmaxf(zr.x, 0.f), gg = 1.0f/(1.0f + __expf(-zg.x));
        ov.x = x*gg + (1.0f - gg)*hv.x;
    }
    {
        float x = fmaxf(zr.y, 0.f), gg = 1.0f/(1.0f + __expf(-zg.y));
        ov.y = x*gg + (1.0f - gg)*hv.y;
    }
    {
        float x = fmaxf(zr.z, 0.f), gg = 1.0f/(1.0f + __expf(-zg.z));
        ov.z = x*gg + (1.0f - gg)*hv.z;
    }
    {
        float x = fmaxf(zr.w, 0.f), gg = 1.0f/(1.0f + __expf(-zg.w));
        ov.w = x*gg + (1.0f - gg)*hv.w;
    }
    *(float4*)(o + (size_t)r*128 + q*4) = ov;
}

// ---------------------------------------------------------------------------
extern "C" void kernel_launch(void* const* d_in, const int* in_sizes, int n_in,
                              void* d_out, int out_size)
{
    const float* h   = (const float*)d_in[0];
    const int*   hm  = (const int*)  d_in[1];
    const float* Bt  = (const float*)d_in[2];
    const float* W1w = (const float*)d_in[3];
    const float* W1b = (const float*)d_in[4];
    const float* W2w = (const float*)d_in[5];
    const float* W2b = (const float*)d_in[6];
    const float* gam = (const float*)d_in[7];
    const float* Wrw = (const float*)d_in[8];
    const float* Wgw = (const float*)d_in[9];

    float* o_out    = (float*)d_out;                 // (c,b,d)
    float* bnew_out = (float*)d_out + (size_t)CB*D;  // (b,i,j)

    const int BNEW_SMEM = 3*BUF2_B;        // 110592 -> 2 CTAs/SM
    const int MMA_SMEM  = 2*BUF4_B;        // 147456
    const int ESP_SMEM  = 128*ETS*4;       // 67584
    cudaFuncSetAttribute(bnew_mma_kernel, cudaFuncAttributeMaxDynamicSharedMemorySize, BNEW_SMEM);
    cudaFuncSetAttribute(htmp_mma_kernel, cudaFuncAttributeMaxDynamicSharedMemorySize, MMA_SMEM);
    cudaFuncSetAttribute(gate_mma_kernel, cudaFuncAttributeMaxDynamicSharedMemorySize, MMA_SMEM);
    cudaFuncSetAttribute(esplit_kernel, cudaFuncAttributeMaxDynamicSharedMemorySize, ESP_SMEM);

    wsplit_kernel<<<256*384/256, 256>>>(Wrw, Wgw);   // also zeroes sums
    fc_kernel<<<dim3(CB/64, 4), 256>>>(h, W1w, W1b, W2w, W2b);
    ht_transpose_kernel<<<dim3(C/32, D/32, BATCH), 256>>>(h);
    esplit_kernel<<<dim3(8, 8, BATCH), 256, ESP_SMEM>>>(Bt, hm);
    bnew_mma_kernel<<<dim3(C/128, C/128, BATCH), 256, BNEW_SMEM>>>(gam, hm, bnew_out);
    htmp_mma_kernel<<<dim3(C/128, BATCH), 256, MMA_SMEM>>>(h);
    gate_mma_kernel<<<dim3(CB/128, 2), 256, MMA_SMEM>>>();
    combine_kernel<<<CB*32/256, 256>>>(h, o_out);
}